// round 13
// baseline (speedup 1.0000x reference)
#include <cuda_runtime.h>
#include <cuda_bf16.h>
#include <math.h>
#include <stdint.h>

#define NN 100000
#define EE 800000
#define DD 128
#define LL 3
#define BN_EPS 1e-5f

// ================= scratch =================
__device__ __align__(16) float g_agg[(size_t)NN * DD];
__device__ __align__(16) float g_x[(size_t)NN * DD];
__device__ __align__(16) float g_y[(size_t)NN * DD];
__device__ int g_deg[NN];
__device__ int g_rowptr[NN + 1];
__device__ int g_cursor[NN];
__device__ int g_csr[EE];
__device__ __align__(16) float g_colsum[DD];
__device__ __align__(16) float g_colsumsq[DD];
__device__ __align__(16) float g_scale[DD];
__device__ __align__(16) float g_shift[DD];
// folded W, pre-split into packed bf16 hi/lo pairs, compact stride-64 tile layout
__device__ __align__(16) uint32_t g_wlh[DD * 64];
__device__ __align__(16) uint32_t g_wll[DD * 64];
__device__ __align__(16) uint32_t g_wrh[DD * 64];
__device__ __align__(16) uint32_t g_wrl[DD * 64];
__device__ __align__(16) float g_b2[DD];    // b + sh@Wr^T
__device__ __align__(16) float g_bwl[DD];   // sh@Wl^T (added only when deg>0)

// ================= CSR build =================
__global__ void k_zero_deg() {
    int i = blockIdx.x * blockDim.x + threadIdx.x;
    if (i < NN) g_deg[i] = 0;
}
__global__ void k_count(const int* __restrict__ dst) {
    int e = blockIdx.x * blockDim.x + threadIdx.x;
    if (e < EE) atomicAdd(&g_deg[dst[e]], 1);
}
__global__ void k_scan() {
    __shared__ int sh[1024];
    int t = threadIdx.x;
    const int CH = (NN + 1023) / 1024;
    int beg = t * CH;
    int end = min(beg + CH, NN);
    int s = 0;
    for (int i = beg; i < end; i++) s += g_deg[i];
    sh[t] = s;
    __syncthreads();
    for (int off = 1; off < 1024; off <<= 1) {
        int v = (t >= off) ? sh[t - off] : 0;
        __syncthreads();
        sh[t] += v;
        __syncthreads();
    }
    int run = sh[t] - s;
    for (int i = beg; i < end; i++) {
        g_rowptr[i] = run;
        g_cursor[i] = run;
        run += g_deg[i];
    }
    if (t == 1023) g_rowptr[NN] = sh[1023];
}
__global__ void k_fill(const int* __restrict__ src, const int* __restrict__ dst) {
    int e = blockIdx.x * blockDim.x + threadIdx.x;
    if (e < EE) {
        int d = dst[e];
        int p = atomicAdd(&g_cursor[d], 1);
        g_csr[p] = src[e];
    }
}

// ================= split helpers =================
__device__ __forceinline__ void split1(float x, uint32_t& hi, uint32_t& lo) {
    __nv_bfloat16 h = __float2bfloat16(x);
    __nv_bfloat16 l = __float2bfloat16(x - __bfloat162float(h));
    hi = (uint32_t)__bfloat16_as_ushort(h);
    lo = (uint32_t)__bfloat16_as_ushort(l);
}
__device__ __forceinline__ void split2(float x, float y, uint32_t& hi, uint32_t& lo) {
    uint32_t h0, l0, h1, l1;
    split1(x, h0, l0);
    split1(y, h1, l1);
    hi = h0 | (h1 << 16);
    lo = l0 | (l1 << 16);
}

// ================= fold: BN(prev stats) into W; emit packed split tiles + bias =================
__global__ void k_fold(const float* __restrict__ Wl, const float* __restrict__ Wr,
                       const float* __restrict__ b,
                       const float* __restrict__ gamma, const float* __restrict__ beta,
                       int ident) {
    __shared__ float red[8];
    int o = blockIdx.x;       // 0..127 output row
    int i = threadIdx.x;      // 0..127 input col
    float sc = 1.f, sh = 0.f;
    if (!ident) {
        float mean = g_colsum[i] / (float)NN;
        float var = g_colsumsq[i] / (float)NN - mean * mean;
        float inv = rsqrtf(var + BN_EPS);
        sc = gamma[i] * inv;
        sh = beta[i] - sc * mean;
    }
    float wl = Wl[o * DD + i];
    float wr = Wr[o * DD + i];
    float wls = wl * sc;
    float wrs = wr * sc;
    if (o == 0) { g_colsum[i] = 0.f; g_colsumsq[i] = 0.f; }

    uint32_t lh, ll, rh, rl;
    split1(wls, lh, ll);
    split1(wrs, rh, rl);
    uint32_t lh1 = __shfl_down_sync(0xFFFFFFFF, lh, 1);
    uint32_t ll1 = __shfl_down_sync(0xFFFFFFFF, ll, 1);
    uint32_t rh1 = __shfl_down_sync(0xFFFFFFFF, rh, 1);
    uint32_t rl1 = __shfl_down_sync(0xFFFFFFFF, rl, 1);
    if ((i & 1) == 0) {
        int w = o * 64 + (i >> 1);
        g_wlh[w] = lh | (lh1 << 16);
        g_wll[w] = ll | (ll1 << 16);
        g_wrh[w] = rh | (rh1 << 16);
        g_wrl[w] = rl | (rl1 << 16);
    }
    float a = sh * wl, c2 = sh * wr;
#pragma unroll
    for (int off = 16; off > 0; off >>= 1) {
        a += __shfl_down_sync(0xFFFFFFFF, a, off);
        c2 += __shfl_down_sync(0xFFFFFFFF, c2, off);
    }
    int wid = i >> 5, lid = i & 31;
    if (lid == 0) { red[wid] = a; red[4 + wid] = c2; }
    __syncthreads();
    if (i == 0) {
        g_b2[o] = b[o] + red[4] + red[5] + red[6] + red[7];
        g_bwl[o] = red[0] + red[1] + red[2] + red[3];
    }
}

// ================= aggregation: warp per node, edge loop unrolled 8x (MLP=8) =================
__global__ void k_agg(const float* __restrict__ hext, int sel) {
    const float* xin = (sel == 0) ? hext : (sel == 1 ? (const float*)g_x : (const float*)g_y);
    int warp = (blockIdx.x * blockDim.x + threadIdx.x) >> 5;
    int lane = threadIdx.x & 31;
    if (warp >= NN) return;
    int s0 = g_rowptr[warp];
    int s1 = g_rowptr[warp + 1];
    float4 a0 = make_float4(0.f, 0.f, 0.f, 0.f);
    float4 a1 = a0, a2 = a0, a3 = a0;
    int e = s0;
    for (; e + 8 <= s1; e += 8) {
        int i0 = g_csr[e], i1 = g_csr[e + 1], i2 = g_csr[e + 2], i3 = g_csr[e + 3];
        int i4 = g_csr[e + 4], i5 = g_csr[e + 5], i6 = g_csr[e + 6], i7 = g_csr[e + 7];
        float4 v0 = *(const float4*)(xin + (size_t)i0 * DD + lane * 4);
        float4 v1 = *(const float4*)(xin + (size_t)i1 * DD + lane * 4);
        float4 v2 = *(const float4*)(xin + (size_t)i2 * DD + lane * 4);
        float4 v3 = *(const float4*)(xin + (size_t)i3 * DD + lane * 4);
        float4 v4 = *(const float4*)(xin + (size_t)i4 * DD + lane * 4);
        float4 v5 = *(const float4*)(xin + (size_t)i5 * DD + lane * 4);
        float4 v6 = *(const float4*)(xin + (size_t)i6 * DD + lane * 4);
        float4 v7 = *(const float4*)(xin + (size_t)i7 * DD + lane * 4);
        a0.x += v0.x; a0.y += v0.y; a0.z += v0.z; a0.w += v0.w;
        a1.x += v1.x; a1.y += v1.y; a1.z += v1.z; a1.w += v1.w;
        a2.x += v2.x; a2.y += v2.y; a2.z += v2.z; a2.w += v2.w;
        a3.x += v3.x; a3.y += v3.y; a3.z += v3.z; a3.w += v3.w;
        a0.x += v4.x; a0.y += v4.y; a0.z += v4.z; a0.w += v4.w;
        a1.x += v5.x; a1.y += v5.y; a1.z += v5.z; a1.w += v5.w;
        a2.x += v6.x; a2.y += v6.y; a2.z += v6.z; a2.w += v6.w;
        a3.x += v7.x; a3.y += v7.y; a3.z += v7.z; a3.w += v7.w;
    }
    for (; e + 4 <= s1; e += 4) {
        int i0 = g_csr[e], i1 = g_csr[e + 1], i2 = g_csr[e + 2], i3 = g_csr[e + 3];
        float4 v0 = *(const float4*)(xin + (size_t)i0 * DD + lane * 4);
        float4 v1 = *(const float4*)(xin + (size_t)i1 * DD + lane * 4);
        float4 v2 = *(const float4*)(xin + (size_t)i2 * DD + lane * 4);
        float4 v3 = *(const float4*)(xin + (size_t)i3 * DD + lane * 4);
        a0.x += v0.x; a0.y += v0.y; a0.z += v0.z; a0.w += v0.w;
        a1.x += v1.x; a1.y += v1.y; a1.z += v1.z; a1.w += v1.w;
        a2.x += v2.x; a2.y += v2.y; a2.z += v2.z; a2.w += v2.w;
        a3.x += v3.x; a3.y += v3.y; a3.z += v3.z; a3.w += v3.w;
    }
    for (; e < s1; e++) {
        int i0 = g_csr[e];
        float4 v0 = *(const float4*)(xin + (size_t)i0 * DD + lane * 4);
        a0.x += v0.x; a0.y += v0.y; a0.z += v0.z; a0.w += v0.w;
    }
    a0.x += a1.x + a2.x + a3.x;
    a0.y += a1.y + a2.y + a3.y;
    a0.z += a1.z + a2.z + a3.z;
    a0.w += a1.w + a2.w + a3.w;
    float inv = 1.0f / (float)max(s1 - s0, 1);
    a0.x *= inv; a0.y *= inv; a0.z *= inv; a0.w *= inv;
    *(float4*)(g_agg + (size_t)warp * DD + lane * 4) = a0;
}

// ================= split-bf16 HMMA GEMM: M-tile 64, ldmatrix fragments =================
#define AW_STRIDE 68
#define A_WORDS (64 * AW_STRIDE)      // 4352
#define W_WORDS (128 * AW_STRIDE)     // 8704
#define SW_AH 0
#define SW_AL (SW_AH + A_WORDS)
#define SW_WH (SW_AL + A_WORDS)
#define SW_WL (SW_WH + W_WORDS)
#define SW_SB2  (SW_WL + W_WORDS)     // 26112
#define SW_SBWL (SW_SB2 + 128)
#define SW_SCOL (SW_SBWL + 128)
#define SW_SSQ  (SW_SCOL + 128)
#define SW_SDEG (SW_SSQ + 128)
#define GEMM_SMEM ((SW_SDEG + 64) * 4)   // 106,752 bytes
#define GT 256

__device__ __forceinline__ void mma_bf16(float* c, uint32_t a0, uint32_t a1, uint32_t a2,
                                         uint32_t a3, uint32_t b0, uint32_t b1) {
    asm volatile(
        "mma.sync.aligned.m16n8k16.row.col.f32.bf16.bf16.f32 "
        "{%0,%1,%2,%3}, {%4,%5,%6,%7}, {%8,%9}, {%0,%1,%2,%3};"
        : "+f"(c[0]), "+f"(c[1]), "+f"(c[2]), "+f"(c[3])
        : "r"(a0), "r"(a1), "r"(a2), "r"(a3), "r"(b0), "r"(b1));
}

#define LDMATRIX_X4(r0, r1, r2, r3, addr) \
    asm volatile("ldmatrix.sync.aligned.m8n8.x4.shared.b16 {%0,%1,%2,%3}, [%4];" \
                 : "=r"(r0), "=r"(r1), "=r"(r2), "=r"(r3) : "r"(addr))

__global__ void __launch_bounds__(GT, 2) k_gemm(
    const float* __restrict__ hext, int sel,   // input: 0 hext, 1 g_x, 2 g_y
    int apply_elu,
    float* __restrict__ hext_out)              // output: null -> (sel==0 ? g_x : g_y)
{
    extern __shared__ __align__(16) uint32_t sm[];
    uint32_t* AH = sm + SW_AH;
    uint32_t* AL = sm + SW_AL;
    uint32_t* WH = sm + SW_WH;
    uint32_t* WL = sm + SW_WL;
    float* sb2  = (float*)(sm + SW_SB2);
    float* sbwl = (float*)(sm + SW_SBWL);
    float* scol = (float*)(sm + SW_SCOL);
    float* ssq  = (float*)(sm + SW_SSQ);
    int*   sdeg = (int*)(sm + SW_SDEG);

    const float* hprev = (sel == 0) ? hext : (sel == 1 ? (const float*)g_x : (const float*)g_y);
    float* hout = hext_out ? hext_out : (sel == 0 ? (float*)g_x : (float*)g_y);
    int tid = threadIdx.x;
    int wid = tid >> 5;    // 0..7
    int lid = tid & 31;
    int tq = lid >> 2;
    int tr = lid & 3;
    int row0 = blockIdx.x * 64;
    int m0 = (wid >> 2) * 32;   // 2 m-warps x 4 n-warps, warp tile 32x32
    int n0 = (wid & 3) * 32;

    if (tid < 128) {
        sb2[tid] = g_b2[tid];
        sbwl[tid] = g_bwl[tid];
        scol[tid] = 0.f;
        ssq[tid] = 0.f;
    }
    if (tid < 64) {
        int m = row0 + tid;
        sdeg[tid] = (m < NN) ? (g_rowptr[m + 1] > g_rowptr[m] ? 1 : 0) : 0;
    }

    // ldmatrix lane base addresses (bytes, relative to tile base)
    uint32_t ah_base = (uint32_t)__cvta_generic_to_shared(AH);
    uint32_t wh_base = (uint32_t)__cvta_generic_to_shared(WH);
    int mat = lid >> 3;        // 0..3
    int rin = lid & 7;
    // A mf: matrices (r0-7,k0-7),(r8-15,k0-7),(r0-7,k8-15),(r8-15,k8-15)
    uint32_t aRel0 = (uint32_t)(((m0 + 0 * 16 + rin + (mat & 1) * 8) * AW_STRIDE + (mat >> 1) * 4) * 4);
    uint32_t aRel1 = (uint32_t)(((m0 + 1 * 16 + rin + (mat & 1) * 8) * AW_STRIDE + (mat >> 1) * 4) * 4);
    // B pair np: matrices (nf=np*2+(mat>>1), khalf=mat&1); rows = n
    uint32_t bRel0 = (uint32_t)(((n0 + (0 * 2 + (mat >> 1)) * 8 + rin) * AW_STRIDE + (mat & 1) * 4) * 4);
    uint32_t bRel1 = (uint32_t)(((n0 + (1 * 2 + (mat >> 1)) * 8 + rin) * AW_STRIDE + (mat & 1) * 4) * 4);

    float c[2][4][4];
#pragma unroll
    for (int i = 0; i < 2; i++)
#pragma unroll
        for (int j = 0; j < 4; j++)
#pragma unroll
            for (int r = 0; r < 4; r++) c[i][j][r] = 0.f;

#pragma unroll
    for (int chunk = 0; chunk < 2; chunk++) {
        const float* Asrc = chunk ? hprev : (const float*)g_agg;
        const uint32_t* Wh = chunk ? (const uint32_t*)g_wrh : (const uint32_t*)g_wlh;
        const uint32_t* Wlo = chunk ? (const uint32_t*)g_wrl : (const uint32_t*)g_wll;
        __syncthreads();   // also covers initial smem setup
        // A fill: split 64 rows (vectorized float4 -> 2 packed words)
        for (int p = tid; p < 2048; p += GT) {
            int r = p >> 5;            // 0..63
            int j2 = (p & 31) * 2;     // 0,2,..,62
            int srow = min(row0 + r, NN - 1);
            float4 v = *(const float4*)(Asrc + (size_t)srow * DD + j2 * 2);
            uint32_t h0, l0, h1, l1;
            split2(v.x, v.y, h0, l0);
            split2(v.z, v.w, h1, l1);
            *(uint2*)&AH[r * AW_STRIDE + j2] = make_uint2(h0, h1);
            *(uint2*)&AL[r * AW_STRIDE + j2] = make_uint2(l0, l1);
        }
        // W fill: pure uint4 copy of pre-split tiles
        for (int p = tid; p < 2048; p += GT) {
            int r = p >> 4;            // 0..127
            int j4 = (p & 15) * 4;     // 0,4,..,60
            *(uint4*)&WH[r * AW_STRIDE + j4] = *(const uint4*)&Wh[r * 64 + j4];
            *(uint4*)&WL[r * AW_STRIDE + j4] = *(const uint4*)&Wlo[r * 64 + j4];
        }
        __syncthreads();
#pragma unroll
        for (int term = 0; term < 3; term++) {
            uint32_t aBase = ah_base + ((term == 2) ? (uint32_t)(A_WORDS * 4) : 0u);
            uint32_t wBase = wh_base + ((term == 1) ? (uint32_t)(W_WORDS * 4) : 0u);
#pragma unroll
            for (int step = 0; step < 8; step++) {
                uint32_t koff = (uint32_t)(step * 32);
                uint32_t b00, b01, b10, b11, b20, b21, b30, b31;
                LDMATRIX_X4(b00, b01, b10, b11, wBase + bRel0 + koff);
                LDMATRIX_X4(b20, b21, b30, b31, wBase + bRel1 + koff);
                uint32_t a0, a1, a2, a3;
                LDMATRIX_X4(a0, a1, a2, a3, aBase + aRel0 + koff);
                mma_bf16(c[0][0], a0, a1, a2, a3, b00, b01);
                mma_bf16(c[0][1], a0, a1, a2, a3, b10, b11);
                mma_bf16(c[0][2], a0, a1, a2, a3, b20, b21);
                mma_bf16(c[0][3], a0, a1, a2, a3, b30, b31);
                uint32_t e0, e1, e2, e3;
                LDMATRIX_X4(e0, e1, e2, e3, aBase + aRel1 + koff);
                mma_bf16(c[1][0], e0, e1, e2, e3, b00, b01);
                mma_bf16(c[1][1], e0, e1, e2, e3, b10, b11);
                mma_bf16(c[1][2], e0, e1, e2, e3, b20, b21);
                mma_bf16(c[1][3], e0, e1, e2, e3, b30, b31);
            }
        }
    }

    // ---------- epilogue: folded bias + deg term + ELU + store + fused stats ----------
    float cs[4][2], cq[4][2];
#pragma unroll
    for (int nf = 0; nf < 4; nf++) { cs[nf][0] = cs[nf][1] = cq[nf][0] = cq[nf][1] = 0.f; }

#pragma unroll
    for (int mf = 0; mf < 2; mf++) {
        int nl0 = m0 + mf * 16 + tq;
        int m = row0 + nl0;
        int m2 = m + 8;
        int d0 = sdeg[nl0];
        int d1 = sdeg[nl0 + 8];
#pragma unroll
        for (int nf = 0; nf < 4; nf++) {
            int n = n0 + nf * 8 + tr * 2;
            float base0 = sb2[n], base1 = sb2[n + 1];
            float w0 = sbwl[n], w1 = sbwl[n + 1];
            float v0 = c[mf][nf][0] + base0 + (d0 ? w0 : 0.f);
            float v1 = c[mf][nf][1] + base1 + (d0 ? w1 : 0.f);
            float v2 = c[mf][nf][2] + base0 + (d1 ? w0 : 0.f);
            float v3 = c[mf][nf][3] + base1 + (d1 ? w1 : 0.f);
            if (apply_elu) {
                v0 = v0 > 0.f ? v0 : expm1f(v0);
                v1 = v1 > 0.f ? v1 : expm1f(v1);
                v2 = v2 > 0.f ? v2 : expm1f(v2);
                v3 = v3 > 0.f ? v3 : expm1f(v3);
            }
            if (m < NN) {
                *(float2*)(hout + (size_t)m * DD + n) = make_float2(v0, v1);
                cs[nf][0] += v0; cs[nf][1] += v1;
                cq[nf][0] += v0 * v0; cq[nf][1] += v1 * v1;
            }
            if (m2 < NN) {
                *(float2*)(hout + (size_t)m2 * DD + n) = make_float2(v2, v3);
                cs[nf][0] += v2; cs[nf][1] += v3;
                cq[nf][0] += v2 * v2; cq[nf][1] += v3 * v3;
            }
        }
    }
#pragma unroll
    for (int nf = 0; nf < 4; nf++) {
#pragma unroll
        for (int off = 4; off < 32; off <<= 1) {
            cs[nf][0] += __shfl_xor_sync(0xFFFFFFFF, cs[nf][0], off);
            cs[nf][1] += __shfl_xor_sync(0xFFFFFFFF, cs[nf][1], off);
            cq[nf][0] += __shfl_xor_sync(0xFFFFFFFF, cq[nf][0], off);
            cq[nf][1] += __shfl_xor_sync(0xFFFFFFFF, cq[nf][1], off);
        }
        if (lid < 4) {
            int n = n0 + nf * 8 + tr * 2;
            atomicAdd(&scol[n], cs[nf][0]);
            atomicAdd(&scol[n + 1], cs[nf][1]);
            atomicAdd(&ssq[n], cq[nf][0]);
            atomicAdd(&ssq[n + 1], cq[nf][1]);
        }
    }
    __syncthreads();
    if (tid < 128) {
        atomicAdd(&g_colsum[tid], scol[tid]);
        atomicAdd(&g_colsumsq[tid], ssq[tid]);
    }
}

// ================= BN stats -> scale/shift (final layer only) =================
__global__ void k_stats(const float* __restrict__ gamma, const float* __restrict__ beta) {
    int c = threadIdx.x;
    if (c < DD) {
        float mean = g_colsum[c] / (float)NN;
        float var = g_colsumsq[c] / (float)NN - mean * mean;
        float inv = rsqrtf(var + BN_EPS);
        float gi = gamma[c] * inv;
        g_scale[c] = gi;
        g_shift[c] = beta[c] - gi * mean;
    }
}

// ================= final normalize (in place) =================
__global__ void k_norm(float* __restrict__ buf) {
    int i = blockIdx.x * blockDim.x + threadIdx.x;
    int c4 = i & 31;
    float4 v = ((const float4*)buf)[i];
    float4 sc = ((const float4*)g_scale)[c4];
    float4 sh = ((const float4*)g_shift)[c4];
    v.x = v.x * sc.x + sh.x;
    v.y = v.y * sc.y + sh.y;
    v.z = v.z * sc.z + sh.z;
    v.w = v.w * sc.w + sh.w;
    ((float4*)buf)[i] = v;
}

// ================= eager module load =================
namespace {
struct HXEagerLoad {
    HXEagerLoad() {
        void* p = nullptr;
        cudaGetSymbolAddress(&p, g_agg);
        cudaGetSymbolAddress(&p, g_x);
        cudaGetSymbolAddress(&p, g_y);
        cudaGetSymbolAddress(&p, g_csr);
        cudaGetSymbolAddress(&p, g_wlh);
        cudaFuncAttributes a;
        cudaFuncGetAttributes(&a, k_zero_deg);
        cudaFuncGetAttributes(&a, k_count);
        cudaFuncGetAttributes(&a, k_scan);
        cudaFuncGetAttributes(&a, k_fill);
        cudaFuncGetAttributes(&a, k_stats);
        cudaFuncGetAttributes(&a, k_fold);
        cudaFuncGetAttributes(&a, k_agg);
        cudaFuncGetAttributes(&a, k_gemm);
        cudaFuncGetAttributes(&a, k_norm);
        cudaFuncSetAttribute(k_gemm, cudaFuncAttributeMaxDynamicSharedMemorySize, GEMM_SMEM);
        cudaDeviceSynchronize();
    }
};
HXEagerLoad hx_eager_load_;
}  // namespace

// ================= launch =================
extern "C" void kernel_launch(void* const* d_in, const int* in_sizes, int n_in,
                              void* d_out, int out_size) {
    (void)in_sizes; (void)n_in; (void)out_size;
    const float* x  = (const float*)d_in[0];
    const int*   ei = (const int*)d_in[1];
    const float* Wl = (const float*)d_in[2];
    const float* Wr = (const float*)d_in[3];
    const float* b  = (const float*)d_in[4];
    const float* gm = (const float*)d_in[5];
    const float* bt = (const float*)d_in[6];
    float* out = (float*)d_out;
    const int* src = ei;
    const int* dst = ei + EE;

    k_zero_deg<<<(NN + 255) / 256, 256>>>();
    k_count<<<(EE + 255) / 256, 256>>>(dst);
    k_scan<<<1, 1024>>>();
    k_fill<<<(EE + 255) / 256, 256>>>(src, dst);

    const int GEMM_GRID = (NN + 63) / 64;  // 1563
    for (int l = 0; l < LL; l++) {
        int sel = (l == 0) ? 0 : (l == 1 ? 1 : 2);
        k_fold<<<128, 128>>>(Wl + l * DD * DD, Wr + l * DD * DD, b + l * DD,
                             gm + (l - 1) * DD, bt + (l - 1) * DD, l == 0 ? 1 : 0);
        k_agg<<<(NN + 7) / 8, 256>>>(x, sel);
        if (l < LL - 1)
            k_gemm<<<GEMM_GRID, GT, GEMM_SMEM>>>(x, sel, 1, nullptr);   // -> g_x / g_y
        else
            k_gemm<<<GEMM_GRID, GT, GEMM_SMEM>>>(x, sel, 0, out);       // -> out
    }
    k_stats<<<1, 128>>>(gm + (LL - 1) * DD, bt + (LL - 1) * DD);
    k_norm<<<NN * 32 / 256, 256>>>(out);
}

// round 14
// speedup vs baseline: 1.0613x; 1.0613x over previous
#include <cuda_runtime.h>
#include <cuda_bf16.h>
#include <math.h>
#include <stdint.h>

#define NN 100000
#define EE 800000
#define DD 128
#define LL 3
#define BN_EPS 1e-5f

// ================= scratch =================
__device__ __align__(16) float g_agg[(size_t)NN * DD];
__device__ __align__(16) float g_x[(size_t)NN * DD];
__device__ __align__(16) float g_y[(size_t)NN * DD];
__device__ int g_deg[NN];
__device__ int g_rowptr[NN + 1];
__device__ int g_cursor[NN];
__device__ int g_csr[EE];
__device__ __align__(16) float g_colsum[DD];
__device__ __align__(16) float g_colsumsq[DD];
__device__ __align__(16) float g_scale[DD];
__device__ __align__(16) float g_shift[DD];
// folded W, pre-split into packed bf16 hi/lo pairs, compact stride-64 tile layout
__device__ __align__(16) uint32_t g_wlh[DD * 64];
__device__ __align__(16) uint32_t g_wll[DD * 64];
__device__ __align__(16) uint32_t g_wrh[DD * 64];
__device__ __align__(16) uint32_t g_wrl[DD * 64];
__device__ __align__(16) float g_b2[DD];    // b + sh@Wr^T
__device__ __align__(16) float g_bwl[DD];   // sh@Wl^T (added only when deg>0)

// ================= CSR build =================
__global__ void k_zero_deg() {
    int i = blockIdx.x * blockDim.x + threadIdx.x;
    if (i < NN) g_deg[i] = 0;
}
__global__ void k_count(const int* __restrict__ dst) {
    int e = blockIdx.x * blockDim.x + threadIdx.x;
    if (e < EE) atomicAdd(&g_deg[dst[e]], 1);
}
__global__ void k_scan() {
    __shared__ int sh[1024];
    int t = threadIdx.x;
    const int CH = (NN + 1023) / 1024;
    int beg = t * CH;
    int end = min(beg + CH, NN);
    int s = 0;
    for (int i = beg; i < end; i++) s += g_deg[i];
    sh[t] = s;
    __syncthreads();
    for (int off = 1; off < 1024; off <<= 1) {
        int v = (t >= off) ? sh[t - off] : 0;
        __syncthreads();
        sh[t] += v;
        __syncthreads();
    }
    int run = sh[t] - s;
    for (int i = beg; i < end; i++) {
        g_rowptr[i] = run;
        g_cursor[i] = run;
        run += g_deg[i];
    }
    if (t == 1023) g_rowptr[NN] = sh[1023];
}
__global__ void k_fill(const int* __restrict__ src, const int* __restrict__ dst) {
    int e = blockIdx.x * blockDim.x + threadIdx.x;
    if (e < EE) {
        int d = dst[e];
        int p = atomicAdd(&g_cursor[d], 1);
        g_csr[p] = src[e];
    }
}

// ================= split helpers =================
__device__ __forceinline__ void split1(float x, uint32_t& hi, uint32_t& lo) {
    __nv_bfloat16 h = __float2bfloat16(x);
    __nv_bfloat16 l = __float2bfloat16(x - __bfloat162float(h));
    hi = (uint32_t)__bfloat16_as_ushort(h);
    lo = (uint32_t)__bfloat16_as_ushort(l);
}
__device__ __forceinline__ void split2(float x, float y, uint32_t& hi, uint32_t& lo) {
    uint32_t h0, l0, h1, l1;
    split1(x, h0, l0);
    split1(y, h1, l1);
    hi = h0 | (h1 << 16);
    lo = l0 | (l1 << 16);
}

// ================= fold: BN(prev stats) into W; emit packed split tiles + bias =================
__global__ void k_fold(const float* __restrict__ Wl, const float* __restrict__ Wr,
                       const float* __restrict__ b,
                       const float* __restrict__ gamma, const float* __restrict__ beta,
                       int ident) {
    __shared__ float red[8];
    int o = blockIdx.x;       // 0..127 output row
    int i = threadIdx.x;      // 0..127 input col
    float sc = 1.f, sh = 0.f;
    if (!ident) {
        float mean = g_colsum[i] / (float)NN;
        float var = g_colsumsq[i] / (float)NN - mean * mean;
        float inv = rsqrtf(var + BN_EPS);
        sc = gamma[i] * inv;
        sh = beta[i] - sc * mean;
    }
    float wl = Wl[o * DD + i];
    float wr = Wr[o * DD + i];
    float wls = wl * sc;
    float wrs = wr * sc;
    if (o == 0) { g_colsum[i] = 0.f; g_colsumsq[i] = 0.f; }

    uint32_t lh, ll, rh, rl;
    split1(wls, lh, ll);
    split1(wrs, rh, rl);
    uint32_t lh1 = __shfl_down_sync(0xFFFFFFFF, lh, 1);
    uint32_t ll1 = __shfl_down_sync(0xFFFFFFFF, ll, 1);
    uint32_t rh1 = __shfl_down_sync(0xFFFFFFFF, rh, 1);
    uint32_t rl1 = __shfl_down_sync(0xFFFFFFFF, rl, 1);
    if ((i & 1) == 0) {
        int w = o * 64 + (i >> 1);
        g_wlh[w] = lh | (lh1 << 16);
        g_wll[w] = ll | (ll1 << 16);
        g_wrh[w] = rh | (rh1 << 16);
        g_wrl[w] = rl | (rl1 << 16);
    }
    float a = sh * wl, c2 = sh * wr;
#pragma unroll
    for (int off = 16; off > 0; off >>= 1) {
        a += __shfl_down_sync(0xFFFFFFFF, a, off);
        c2 += __shfl_down_sync(0xFFFFFFFF, c2, off);
    }
    int wid = i >> 5, lid = i & 31;
    if (lid == 0) { red[wid] = a; red[4 + wid] = c2; }
    __syncthreads();
    if (i == 0) {
        g_b2[o] = b[o] + red[4] + red[5] + red[6] + red[7];
        g_bwl[o] = red[0] + red[1] + red[2] + red[3];
    }
}

// ================= aggregation: 2 nodes per warp, interleaved 4+4 (sustained MLP=8) =====
__global__ void k_agg(const float* __restrict__ hext, int sel) {
    const float* xin = (sel == 0) ? hext : (sel == 1 ? (const float*)g_x : (const float*)g_y);
    int warp = (blockIdx.x * blockDim.x + threadIdx.x) >> 5;
    int lane = threadIdx.x & 31;
    int nA = warp * 2;
    int nB = nA + 1;
    if (nA >= NN) return;
    int ea = g_rowptr[nA];
    int s1a = g_rowptr[nA + 1];
    int eb = 0, s1b = 0;
    if (nB < NN) { eb = g_rowptr[nB]; s1b = g_rowptr[nB + 1]; }
    int degA = s1a - ea;
    int degB = s1b - eb;

    float4 aA0 = make_float4(0.f, 0.f, 0.f, 0.f), aA1 = aA0;
    float4 aB0 = aA0, aB1 = aA0;

    // joint loop: 4 independent loads per node -> 8 in flight
    while (ea + 4 <= s1a && eb + 4 <= s1b) {
        int i0 = g_csr[ea], i1 = g_csr[ea + 1], i2 = g_csr[ea + 2], i3 = g_csr[ea + 3];
        int j0 = g_csr[eb], j1 = g_csr[eb + 1], j2 = g_csr[eb + 2], j3 = g_csr[eb + 3];
        float4 u0 = *(const float4*)(xin + (size_t)i0 * DD + lane * 4);
        float4 u1 = *(const float4*)(xin + (size_t)i1 * DD + lane * 4);
        float4 u2 = *(const float4*)(xin + (size_t)i2 * DD + lane * 4);
        float4 u3 = *(const float4*)(xin + (size_t)i3 * DD + lane * 4);
        float4 w0 = *(const float4*)(xin + (size_t)j0 * DD + lane * 4);
        float4 w1 = *(const float4*)(xin + (size_t)j1 * DD + lane * 4);
        float4 w2 = *(const float4*)(xin + (size_t)j2 * DD + lane * 4);
        float4 w3 = *(const float4*)(xin + (size_t)j3 * DD + lane * 4);
        aA0.x += u0.x; aA0.y += u0.y; aA0.z += u0.z; aA0.w += u0.w;
        aA1.x += u1.x; aA1.y += u1.y; aA1.z += u1.z; aA1.w += u1.w;
        aA0.x += u2.x; aA0.y += u2.y; aA0.z += u2.z; aA0.w += u2.w;
        aA1.x += u3.x; aA1.y += u3.y; aA1.z += u3.z; aA1.w += u3.w;
        aB0.x += w0.x; aB0.y += w0.y; aB0.z += w0.z; aB0.w += w0.w;
        aB1.x += w1.x; aB1.y += w1.y; aB1.z += w1.z; aB1.w += w1.w;
        aB0.x += w2.x; aB0.y += w2.y; aB0.z += w2.z; aB0.w += w2.w;
        aB1.x += w3.x; aB1.y += w3.y; aB1.z += w3.z; aB1.w += w3.w;
        ea += 4;
        eb += 4;
    }
    // finish node A
    for (; ea + 4 <= s1a; ea += 4) {
        int i0 = g_csr[ea], i1 = g_csr[ea + 1], i2 = g_csr[ea + 2], i3 = g_csr[ea + 3];
        float4 u0 = *(const float4*)(xin + (size_t)i0 * DD + lane * 4);
        float4 u1 = *(const float4*)(xin + (size_t)i1 * DD + lane * 4);
        float4 u2 = *(const float4*)(xin + (size_t)i2 * DD + lane * 4);
        float4 u3 = *(const float4*)(xin + (size_t)i3 * DD + lane * 4);
        aA0.x += u0.x; aA0.y += u0.y; aA0.z += u0.z; aA0.w += u0.w;
        aA1.x += u1.x; aA1.y += u1.y; aA1.z += u1.z; aA1.w += u1.w;
        aA0.x += u2.x; aA0.y += u2.y; aA0.z += u2.z; aA0.w += u2.w;
        aA1.x += u3.x; aA1.y += u3.y; aA1.z += u3.z; aA1.w += u3.w;
    }
    for (; ea < s1a; ea++) {
        int i0 = g_csr[ea];
        float4 u0 = *(const float4*)(xin + (size_t)i0 * DD + lane * 4);
        aA0.x += u0.x; aA0.y += u0.y; aA0.z += u0.z; aA0.w += u0.w;
    }
    // finish node B
    for (; eb + 4 <= s1b; eb += 4) {
        int j0 = g_csr[eb], j1 = g_csr[eb + 1], j2 = g_csr[eb + 2], j3 = g_csr[eb + 3];
        float4 w0 = *(const float4*)(xin + (size_t)j0 * DD + lane * 4);
        float4 w1 = *(const float4*)(xin + (size_t)j1 * DD + lane * 4);
        float4 w2 = *(const float4*)(xin + (size_t)j2 * DD + lane * 4);
        float4 w3 = *(const float4*)(xin + (size_t)j3 * DD + lane * 4);
        aB0.x += w0.x; aB0.y += w0.y; aB0.z += w0.z; aB0.w += w0.w;
        aB1.x += w1.x; aB1.y += w1.y; aB1.z += w1.z; aB1.w += w1.w;
        aB0.x += w2.x; aB0.y += w2.y; aB0.z += w2.z; aB0.w += w2.w;
        aB1.x += w3.x; aB1.y += w3.y; aB1.z += w3.z; aB1.w += w3.w;
    }
    for (; eb < s1b; eb++) {
        int j0 = g_csr[eb];
        float4 w0 = *(const float4*)(xin + (size_t)j0 * DD + lane * 4);
        aB0.x += w0.x; aB0.y += w0.y; aB0.z += w0.z; aB0.w += w0.w;
    }

    float invA = 1.0f / (float)max(degA, 1);
    aA0.x = (aA0.x + aA1.x) * invA;
    aA0.y = (aA0.y + aA1.y) * invA;
    aA0.z = (aA0.z + aA1.z) * invA;
    aA0.w = (aA0.w + aA1.w) * invA;
    *(float4*)(g_agg + (size_t)nA * DD + lane * 4) = aA0;
    if (nB < NN) {
        float invB = 1.0f / (float)max(degB, 1);
        aB0.x = (aB0.x + aB1.x) * invB;
        aB0.y = (aB0.y + aB1.y) * invB;
        aB0.z = (aB0.z + aB1.z) * invB;
        aB0.w = (aB0.w + aB1.w) * invB;
        *(float4*)(g_agg + (size_t)nB * DD + lane * 4) = aB0;
    }
}

// ================= split-bf16 HMMA GEMM: M-tile 64, 256 thr, 2 blocks/SM =================
#define AW_STRIDE 68
#define A_WORDS (64 * AW_STRIDE)      // 4352
#define W_WORDS (128 * AW_STRIDE)     // 8704
#define SW_AH 0
#define SW_AL (SW_AH + A_WORDS)
#define SW_WH (SW_AL + A_WORDS)
#define SW_WL (SW_WH + W_WORDS)
#define SW_SB2  (SW_WL + W_WORDS)     // 26112
#define SW_SBWL (SW_SB2 + 128)
#define SW_SCOL (SW_SBWL + 128)
#define SW_SSQ  (SW_SCOL + 128)
#define SW_SDEG (SW_SSQ + 128)
#define GEMM_SMEM ((SW_SDEG + 64) * 4)   // 106,752 bytes
#define GT 256

__device__ __forceinline__ void mma_bf16(float* c, uint32_t a0, uint32_t a1, uint32_t a2,
                                         uint32_t a3, uint32_t b0, uint32_t b1) {
    asm volatile(
        "mma.sync.aligned.m16n8k16.row.col.f32.bf16.bf16.f32 "
        "{%0,%1,%2,%3}, {%4,%5,%6,%7}, {%8,%9}, {%0,%1,%2,%3};"
        : "+f"(c[0]), "+f"(c[1]), "+f"(c[2]), "+f"(c[3])
        : "r"(a0), "r"(a1), "r"(a2), "r"(a3), "r"(b0), "r"(b1));
}

__global__ void __launch_bounds__(GT, 2) k_gemm(
    const float* __restrict__ hext, int sel,   // input: 0 hext, 1 g_x, 2 g_y
    int apply_elu,
    float* __restrict__ hext_out)              // output: null -> (sel==0 ? g_x : g_y)
{
    extern __shared__ __align__(16) uint32_t sm[];
    uint32_t* AH = sm + SW_AH;
    uint32_t* AL = sm + SW_AL;
    uint32_t* WH = sm + SW_WH;
    uint32_t* WL = sm + SW_WL;
    float* sb2  = (float*)(sm + SW_SB2);
    float* sbwl = (float*)(sm + SW_SBWL);
    float* scol = (float*)(sm + SW_SCOL);
    float* ssq  = (float*)(sm + SW_SSQ);
    int*   sdeg = (int*)(sm + SW_SDEG);

    const float* hprev = (sel == 0) ? hext : (sel == 1 ? (const float*)g_x : (const float*)g_y);
    float* hout = hext_out ? hext_out : (sel == 0 ? (float*)g_x : (float*)g_y);
    int tid = threadIdx.x;
    int wid = tid >> 5;    // 0..7
    int lid = tid & 31;
    int tq = lid >> 2;
    int tr = lid & 3;
    int row0 = blockIdx.x * 64;
    int m0 = (wid >> 2) * 32;   // 2 m-warps x 4 n-warps, warp tile 32x32
    int n0 = (wid & 3) * 32;

    if (tid < 128) {
        sb2[tid] = g_b2[tid];
        sbwl[tid] = g_bwl[tid];
        scol[tid] = 0.f;
        ssq[tid] = 0.f;
    }
    if (tid < 64) {
        int m = row0 + tid;
        sdeg[tid] = (m < NN) ? (g_rowptr[m + 1] > g_rowptr[m] ? 1 : 0) : 0;
    }

    float c[2][4][4];
#pragma unroll
    for (int i = 0; i < 2; i++)
#pragma unroll
        for (int j = 0; j < 4; j++)
#pragma unroll
            for (int r = 0; r < 4; r++) c[i][j][r] = 0.f;

#pragma unroll
    for (int chunk = 0; chunk < 2; chunk++) {
        const float* Asrc = chunk ? hprev : (const float*)g_agg;
        const uint32_t* Wh = chunk ? (const uint32_t*)g_wrh : (const uint32_t*)g_wlh;
        const uint32_t* Wlo = chunk ? (const uint32_t*)g_wrl : (const uint32_t*)g_wll;
        __syncthreads();   // also covers initial smem setup
        // A fill: split 64 rows (vectorized float4 -> 2 packed words)
        for (int p = tid; p < 2048; p += GT) {
            int r = p >> 5;            // 0..63
            int j2 = (p & 31) * 2;     // 0,2,..,62
            int srow = min(row0 + r, NN - 1);
            float4 v = *(const float4*)(Asrc + (size_t)srow * DD + j2 * 2);
            uint32_t h0, l0, h1, l1;
            split2(v.x, v.y, h0, l0);
            split2(v.z, v.w, h1, l1);
            *(uint2*)&AH[r * AW_STRIDE + j2] = make_uint2(h0, h1);
            *(uint2*)&AL[r * AW_STRIDE + j2] = make_uint2(l0, l1);
        }
        // W fill: pure uint4 copy of pre-split tiles
        for (int p = tid; p < 2048; p += GT) {
            int r = p >> 4;            // 0..127
            int j4 = (p & 15) * 4;     // 0,4,..,60
            *(uint4*)&WH[r * AW_STRIDE + j4] = *(const uint4*)&Wh[r * 64 + j4];
            *(uint4*)&WL[r * AW_STRIDE + j4] = *(const uint4*)&Wlo[r * 64 + j4];
        }
        __syncthreads();
#pragma unroll
        for (int term = 0; term < 3; term++) {
            const uint32_t* Ap = (term == 2) ? AL : AH;
            const uint32_t* Wp = (term == 1) ? WL : WH;
#pragma unroll
            for (int step = 0; step < 8; step++) {
                int kw = step * 8 + tr;
                uint32_t bfr[4][2];
#pragma unroll
                for (int nf = 0; nf < 4; nf++) {
                    const uint32_t* bp = Wp + (n0 + nf * 8 + tq) * AW_STRIDE;
                    bfr[nf][0] = bp[kw];
                    bfr[nf][1] = bp[kw + 4];
                }
#pragma unroll
                for (int mf = 0; mf < 2; mf++) {
                    const uint32_t* ap0 = Ap + (m0 + mf * 16 + tq) * AW_STRIDE;
                    const uint32_t* ap1 = ap0 + 8 * AW_STRIDE;
                    uint32_t a0 = ap0[kw];
                    uint32_t a1 = ap1[kw];
                    uint32_t a2 = ap0[kw + 4];
                    uint32_t a3 = ap1[kw + 4];
#pragma unroll
                    for (int nf = 0; nf < 4; nf++)
                        mma_bf16(c[mf][nf], a0, a1, a2, a3, bfr[nf][0], bfr[nf][1]);
                }
            }
        }
    }

    // ---------- epilogue: folded bias + deg term + ELU + store + fused stats ----------
    float cs[4][2], cq[4][2];
#pragma unroll
    for (int nf = 0; nf < 4; nf++) { cs[nf][0] = cs[nf][1] = cq[nf][0] = cq[nf][1] = 0.f; }

#pragma unroll
    for (int mf = 0; mf < 2; mf++) {
        int nl0 = m0 + mf * 16 + tq;
        int m = row0 + nl0;
        int m2 = m + 8;
        int d0 = sdeg[nl0];
        int d1 = sdeg[nl0 + 8];
#pragma unroll
        for (int nf = 0; nf < 4; nf++) {
            int n = n0 + nf * 8 + tr * 2;
            float base0 = sb2[n], base1 = sb2[n + 1];
            float w0 = sbwl[n], w1 = sbwl[n + 1];
            float v0 = c[mf][nf][0] + base0 + (d0 ? w0 : 0.f);
            float v1 = c[mf][nf][1] + base1 + (d0 ? w1 : 0.f);
            float v2 = c[mf][nf][2] + base0 + (d1 ? w0 : 0.f);
            float v3 = c[mf][nf][3] + base1 + (d1 ? w1 : 0.f);
            if (apply_elu) {
                v0 = v0 > 0.f ? v0 : expm1f(v0);
                v1 = v1 > 0.f ? v1 : expm1f(v1);
                v2 = v2 > 0.f ? v2 : expm1f(v2);
                v3 = v3 > 0.f ? v3 : expm1f(v3);
            }
            if (m < NN) {
                *(float2*)(hout + (size_t)m * DD + n) = make_float2(v0, v1);
                cs[nf][0] += v0; cs[nf][1] += v1;
                cq[nf][0] += v0 * v0; cq[nf][1] += v1 * v1;
            }
            if (m2 < NN) {
                *(float2*)(hout + (size_t)m2 * DD + n) = make_float2(v2, v3);
                cs[nf][0] += v2; cs[nf][1] += v3;
                cq[nf][0] += v2 * v2; cq[nf][1] += v3 * v3;
            }
        }
    }
#pragma unroll
    for (int nf = 0; nf < 4; nf++) {
#pragma unroll
        for (int off = 4; off < 32; off <<= 1) {
            cs[nf][0] += __shfl_xor_sync(0xFFFFFFFF, cs[nf][0], off);
            cs[nf][1] += __shfl_xor_sync(0xFFFFFFFF, cs[nf][1], off);
            cq[nf][0] += __shfl_xor_sync(0xFFFFFFFF, cq[nf][0], off);
            cq[nf][1] += __shfl_xor_sync(0xFFFFFFFF, cq[nf][1], off);
        }
        if (lid < 4) {
            int n = n0 + nf * 8 + tr * 2;
            atomicAdd(&scol[n], cs[nf][0]);
            atomicAdd(&scol[n + 1], cs[nf][1]);
            atomicAdd(&ssq[n], cq[nf][0]);
            atomicAdd(&ssq[n + 1], cq[nf][1]);
        }
    }
    __syncthreads();
    if (tid < 128) {
        atomicAdd(&g_colsum[tid], scol[tid]);
        atomicAdd(&g_colsumsq[tid], ssq[tid]);
    }
}

// ================= BN stats -> scale/shift (final layer only) =================
__global__ void k_stats(const float* __restrict__ gamma, const float* __restrict__ beta) {
    int c = threadIdx.x;
    if (c < DD) {
        float mean = g_colsum[c] / (float)NN;
        float var = g_colsumsq[c] / (float)NN - mean * mean;
        float inv = rsqrtf(var + BN_EPS);
        float gi = gamma[c] * inv;
        g_scale[c] = gi;
        g_shift[c] = beta[c] - gi * mean;
    }
}

// ================= final normalize (in place) =================
__global__ void k_norm(float* __restrict__ buf) {
    int i = blockIdx.x * blockDim.x + threadIdx.x;
    int c4 = i & 31;
    float4 v = ((const float4*)buf)[i];
    float4 sc = ((const float4*)g_scale)[c4];
    float4 sh = ((const float4*)g_shift)[c4];
    v.x = v.x * sc.x + sh.x;
    v.y = v.y * sc.y + sh.y;
    v.z = v.z * sc.z + sh.z;
    v.w = v.w * sc.w + sh.w;
    ((float4*)buf)[i] = v;
}

// ================= eager module load =================
namespace {
struct HXEagerLoad {
    HXEagerLoad() {
        void* p = nullptr;
        cudaGetSymbolAddress(&p, g_agg);
        cudaGetSymbolAddress(&p, g_x);
        cudaGetSymbolAddress(&p, g_y);
        cudaGetSymbolAddress(&p, g_csr);
        cudaGetSymbolAddress(&p, g_wlh);
        cudaFuncAttributes a;
        cudaFuncGetAttributes(&a, k_zero_deg);
        cudaFuncGetAttributes(&a, k_count);
        cudaFuncGetAttributes(&a, k_scan);
        cudaFuncGetAttributes(&a, k_fill);
        cudaFuncGetAttributes(&a, k_stats);
        cudaFuncGetAttributes(&a, k_fold);
        cudaFuncGetAttributes(&a, k_agg);
        cudaFuncGetAttributes(&a, k_gemm);
        cudaFuncGetAttributes(&a, k_norm);
        cudaFuncSetAttribute(k_gemm, cudaFuncAttributeMaxDynamicSharedMemorySize, GEMM_SMEM);
        cudaDeviceSynchronize();
    }
};
HXEagerLoad hx_eager_load_;
}  // namespace

// ================= launch =================
extern "C" void kernel_launch(void* const* d_in, const int* in_sizes, int n_in,
                              void* d_out, int out_size) {
    (void)in_sizes; (void)n_in; (void)out_size;
    const float* x  = (const float*)d_in[0];
    const int*   ei = (const int*)d_in[1];
    const float* Wl = (const float*)d_in[2];
    const float* Wr = (const float*)d_in[3];
    const float* b  = (const float*)d_in[4];
    const float* gm = (const float*)d_in[5];
    const float* bt = (const float*)d_in[6];
    float* out = (float*)d_out;
    const int* src = ei;
    const int* dst = ei + EE;

    k_zero_deg<<<(NN + 255) / 256, 256>>>();
    k_count<<<(EE + 255) / 256, 256>>>(dst);
    k_scan<<<1, 1024>>>();
    k_fill<<<(EE + 255) / 256, 256>>>(src, dst);

    const int GEMM_GRID = (NN + 63) / 64;  // 1563
    const int AGG_GRID = (NN / 2 + 7) / 8; // 2 nodes/warp, 8 warps/block
    for (int l = 0; l < LL; l++) {
        int sel = (l == 0) ? 0 : (l == 1 ? 1 : 2);
        k_fold<<<128, 128>>>(Wl + l * DD * DD, Wr + l * DD * DD, b + l * DD,
                             gm + (l - 1) * DD, bt + (l - 1) * DD, l == 0 ? 1 : 0);
        k_agg<<<AGG_GRID, 256>>>(x, sel);
        if (l < LL - 1)
            k_gemm<<<GEMM_GRID, GT, GEMM_SMEM>>>(x, sel, 1, nullptr);   // -> g_x / g_y
        else
            k_gemm<<<GEMM_GRID, GT, GEMM_SMEM>>>(x, sel, 0, out);       // -> out
    }
    k_stats<<<1, 128>>>(gm + (LL - 1) * DD, bt + (LL - 1) * DD);
    k_norm<<<NN * 32 / 256, 256>>>(out);
}

// round 15
// speedup vs baseline: 1.0761x; 1.0140x over previous
#include <cuda_runtime.h>
#include <cuda_bf16.h>
#include <cuda_fp16.h>
#include <math.h>
#include <stdint.h>

#define NN 100000
#define EE 800000
#define DD 128
#define LL 3
#define BN_EPS 1e-5f

// ================= scratch =================
__device__ __align__(16) float g_agg[(size_t)NN * DD];
__device__ __align__(16) float g_x[(size_t)NN * DD];
__device__ __align__(16) float g_y[(size_t)NN * DD];
__device__ __align__(16) __half g_h16[(size_t)NN * DD];   // fp16 mirror of current layer input
__device__ int g_deg[NN];
__device__ int g_rowptr[NN + 1];
__device__ int g_cursor[NN];
__device__ int g_csr[EE];
__device__ __align__(16) float g_colsum[DD];
__device__ __align__(16) float g_colsumsq[DD];
__device__ __align__(16) float g_scale[DD];
__device__ __align__(16) float g_shift[DD];
// folded W, pre-split into packed bf16 hi/lo pairs, compact stride-64 tile layout
__device__ __align__(16) uint32_t g_wlh[DD * 64];
__device__ __align__(16) uint32_t g_wll[DD * 64];
__device__ __align__(16) uint32_t g_wrh[DD * 64];
__device__ __align__(16) uint32_t g_wrl[DD * 64];
__device__ __align__(16) float g_b2[DD];    // b + sh@Wr^T
__device__ __align__(16) float g_bwl[DD];   // sh@Wl^T (added only when deg>0)

// ================= CSR build =================
// k_count also converts x -> g_h16 (fp16 mirror for layer-0 gather)
__global__ void k_count_cvt(const int* __restrict__ dst, const float* __restrict__ x) {
    int t = blockIdx.x * blockDim.x + threadIdx.x;
    if (t < EE) atomicAdd(&g_deg[dst[t]], 1);
    for (int i = t; i < NN * DD / 4; i += gridDim.x * blockDim.x) {
        float4 v = ((const float4*)x)[i];
        __half2* o = (__half2*)g_h16;
        o[i * 2] = __floats2half2_rn(v.x, v.y);
        o[i * 2 + 1] = __floats2half2_rn(v.z, v.w);
    }
}
__global__ void k_scan() {
    __shared__ int sh[1024];
    int t = threadIdx.x;
    const int CH = (NN + 1023) / 1024;
    int beg = t * CH;
    int end = min(beg + CH, NN);
    int s = 0;
    for (int i = beg; i < end; i++) s += g_deg[i];
    sh[t] = s;
    __syncthreads();
    for (int off = 1; off < 1024; off <<= 1) {
        int v = (t >= off) ? sh[t - off] : 0;
        __syncthreads();
        sh[t] += v;
        __syncthreads();
    }
    int run = sh[t] - s;
    for (int i = beg; i < end; i++) {
        g_rowptr[i] = run;
        g_cursor[i] = run;
        run += g_deg[i];
    }
    if (t == 1023) g_rowptr[NN] = sh[1023];
}
__global__ void k_fill(const int* __restrict__ src, const int* __restrict__ dst) {
    int e = blockIdx.x * blockDim.x + threadIdx.x;
    if (e < EE) {
        int d = dst[e];
        int p = atomicAdd(&g_cursor[d], 1);
        g_csr[p] = src[e];
    }
}

// ================= split helpers =================
__device__ __forceinline__ void split1(float x, uint32_t& hi, uint32_t& lo) {
    __nv_bfloat16 h = __float2bfloat16(x);
    __nv_bfloat16 l = __float2bfloat16(x - __bfloat162float(h));
    hi = (uint32_t)__bfloat16_as_ushort(h);
    lo = (uint32_t)__bfloat16_as_ushort(l);
}
__device__ __forceinline__ void split2(float x, float y, uint32_t& hi, uint32_t& lo) {
    uint32_t h0, l0, h1, l1;
    split1(x, h0, l0);
    split1(y, h1, l1);
    hi = h0 | (h1 << 16);
    lo = l0 | (l1 << 16);
}

// ================= fold: BN(prev stats) into W; emit packed split tiles + bias =================
__global__ void k_fold(const float* __restrict__ Wl, const float* __restrict__ Wr,
                       const float* __restrict__ b,
                       const float* __restrict__ gamma, const float* __restrict__ beta,
                       int ident) {
    __shared__ float red[8];
    int o = blockIdx.x;       // 0..127 output row
    int i = threadIdx.x;      // 0..127 input col
    float sc = 1.f, sh = 0.f;
    if (!ident) {
        float mean = g_colsum[i] / (float)NN;
        float var = g_colsumsq[i] / (float)NN - mean * mean;
        float inv = rsqrtf(var + BN_EPS);
        sc = gamma[i] * inv;
        sh = beta[i] - sc * mean;
    }
    float wl = Wl[o * DD + i];
    float wr = Wr[o * DD + i];
    float wls = wl * sc;
    float wrs = wr * sc;
    if (o == 0) { g_colsum[i] = 0.f; g_colsumsq[i] = 0.f; }

    uint32_t lh, ll, rh, rl;
    split1(wls, lh, ll);
    split1(wrs, rh, rl);
    uint32_t lh1 = __shfl_down_sync(0xFFFFFFFF, lh, 1);
    uint32_t ll1 = __shfl_down_sync(0xFFFFFFFF, ll, 1);
    uint32_t rh1 = __shfl_down_sync(0xFFFFFFFF, rh, 1);
    uint32_t rl1 = __shfl_down_sync(0xFFFFFFFF, rl, 1);
    if ((i & 1) == 0) {
        int w = o * 64 + (i >> 1);
        g_wlh[w] = lh | (lh1 << 16);
        g_wll[w] = ll | (ll1 << 16);
        g_wrh[w] = rh | (rh1 << 16);
        g_wrl[w] = rl | (rl1 << 16);
    }
    float a = sh * wl, c2 = sh * wr;
#pragma unroll
    for (int off = 16; off > 0; off >>= 1) {
        a += __shfl_down_sync(0xFFFFFFFF, a, off);
        c2 += __shfl_down_sync(0xFFFFFFFF, c2, off);
    }
    int wid = i >> 5, lid = i & 31;
    if (lid == 0) { red[wid] = a; red[4 + wid] = c2; }
    __syncthreads();
    if (i == 0) {
        g_b2[o] = b[o] + red[4] + red[5] + red[6] + red[7];
        g_bwl[o] = red[0] + red[1] + red[2] + red[3];
    }
}

// ================= aggregation: fp16 gather, 2 nodes/warp interleaved (MLP=8) =============
__device__ __forceinline__ void acc_h4(float4& a, uint2 u) {
    float2 f0 = __half22float2(*(__half2*)&u.x);
    float2 f1 = __half22float2(*(__half2*)&u.y);
    a.x += f0.x; a.y += f0.y; a.z += f1.x; a.w += f1.y;
}

__global__ void k_agg() {
    const uint2* __restrict__ h16 = (const uint2*)g_h16;  // row stride DD/4 uint2
    int warp = (blockIdx.x * blockDim.x + threadIdx.x) >> 5;
    int lane = threadIdx.x & 31;
    int nA = warp * 2;
    int nB = nA + 1;
    if (nA >= NN) return;
    int ea = g_rowptr[nA];
    int s1a = g_rowptr[nA + 1];
    int eb = 0, s1b = 0;
    if (nB < NN) { eb = g_rowptr[nB]; s1b = g_rowptr[nB + 1]; }
    int degA = s1a - ea;
    int degB = s1b - eb;

    float4 aA0 = make_float4(0.f, 0.f, 0.f, 0.f), aA1 = aA0;
    float4 aB0 = aA0, aB1 = aA0;

    while (ea + 4 <= s1a && eb + 4 <= s1b) {
        int i0 = g_csr[ea], i1 = g_csr[ea + 1], i2 = g_csr[ea + 2], i3 = g_csr[ea + 3];
        int j0 = g_csr[eb], j1 = g_csr[eb + 1], j2 = g_csr[eb + 2], j3 = g_csr[eb + 3];
        uint2 u0 = h16[(size_t)i0 * 32 + lane];
        uint2 u1 = h16[(size_t)i1 * 32 + lane];
        uint2 u2 = h16[(size_t)i2 * 32 + lane];
        uint2 u3 = h16[(size_t)i3 * 32 + lane];
        uint2 w0 = h16[(size_t)j0 * 32 + lane];
        uint2 w1 = h16[(size_t)j1 * 32 + lane];
        uint2 w2 = h16[(size_t)j2 * 32 + lane];
        uint2 w3 = h16[(size_t)j3 * 32 + lane];
        acc_h4(aA0, u0); acc_h4(aA1, u1); acc_h4(aA0, u2); acc_h4(aA1, u3);
        acc_h4(aB0, w0); acc_h4(aB1, w1); acc_h4(aB0, w2); acc_h4(aB1, w3);
        ea += 4;
        eb += 4;
    }
    for (; ea + 4 <= s1a; ea += 4) {
        int i0 = g_csr[ea], i1 = g_csr[ea + 1], i2 = g_csr[ea + 2], i3 = g_csr[ea + 3];
        uint2 u0 = h16[(size_t)i0 * 32 + lane];
        uint2 u1 = h16[(size_t)i1 * 32 + lane];
        uint2 u2 = h16[(size_t)i2 * 32 + lane];
        uint2 u3 = h16[(size_t)i3 * 32 + lane];
        acc_h4(aA0, u0); acc_h4(aA1, u1); acc_h4(aA0, u2); acc_h4(aA1, u3);
    }
    for (; ea < s1a; ea++) {
        uint2 u0 = h16[(size_t)g_csr[ea] * 32 + lane];
        acc_h4(aA0, u0);
    }
    for (; eb + 4 <= s1b; eb += 4) {
        int j0 = g_csr[eb], j1 = g_csr[eb + 1], j2 = g_csr[eb + 2], j3 = g_csr[eb + 3];
        uint2 w0 = h16[(size_t)j0 * 32 + lane];
        uint2 w1 = h16[(size_t)j1 * 32 + lane];
        uint2 w2 = h16[(size_t)j2 * 32 + lane];
        uint2 w3 = h16[(size_t)j3 * 32 + lane];
        acc_h4(aB0, w0); acc_h4(aB1, w1); acc_h4(aB0, w2); acc_h4(aB1, w3);
    }
    for (; eb < s1b; eb++) {
        uint2 w0 = h16[(size_t)g_csr[eb] * 32 + lane];
        acc_h4(aB0, w0);
    }

    float invA = 1.0f / (float)max(degA, 1);
    aA0.x = (aA0.x + aA1.x) * invA;
    aA0.y = (aA0.y + aA1.y) * invA;
    aA0.z = (aA0.z + aA1.z) * invA;
    aA0.w = (aA0.w + aA1.w) * invA;
    *(float4*)(g_agg + (size_t)nA * DD + lane * 4) = aA0;
    if (nB < NN) {
        float invB = 1.0f / (float)max(degB, 1);
        aB0.x = (aB0.x + aB1.x) * invB;
        aB0.y = (aB0.y + aB1.y) * invB;
        aB0.z = (aB0.z + aB1.z) * invB;
        aB0.w = (aB0.w + aB1.w) * invB;
        *(float4*)(g_agg + (size_t)nB * DD + lane * 4) = aB0;
    }
}

// ================= split-bf16 HMMA GEMM: M-tile 64, 256 thr, 2 blocks/SM =================
#define AW_STRIDE 68
#define A_WORDS (64 * AW_STRIDE)      // 4352
#define W_WORDS (128 * AW_STRIDE)     // 8704
#define SW_AH 0
#define SW_AL (SW_AH + A_WORDS)
#define SW_WH (SW_AL + A_WORDS)
#define SW_WL (SW_WH + W_WORDS)
#define SW_SB2  (SW_WL + W_WORDS)     // 26112
#define SW_SBWL (SW_SB2 + 128)
#define SW_SCOL (SW_SBWL + 128)
#define SW_SSQ  (SW_SCOL + 128)
#define SW_SDEG (SW_SSQ + 128)
#define GEMM_SMEM ((SW_SDEG + 64) * 4)   // 106,752 bytes
#define GT 256

__device__ __forceinline__ void mma_bf16(float* c, uint32_t a0, uint32_t a1, uint32_t a2,
                                         uint32_t a3, uint32_t b0, uint32_t b1) {
    asm volatile(
        "mma.sync.aligned.m16n8k16.row.col.f32.bf16.bf16.f32 "
        "{%0,%1,%2,%3}, {%4,%5,%6,%7}, {%8,%9}, {%0,%1,%2,%3};"
        : "+f"(c[0]), "+f"(c[1]), "+f"(c[2]), "+f"(c[3])
        : "r"(a0), "r"(a1), "r"(a2), "r"(a3), "r"(b0), "r"(b1));
}

__global__ void __launch_bounds__(GT, 2) k_gemm(
    const float* __restrict__ hext, int sel,   // input: 0 hext, 1 g_x, 2 g_y
    int apply_elu,
    float* __restrict__ hext_out)              // output: null -> (sel==0 ? g_x : g_y)
{
    extern __shared__ __align__(16) uint32_t sm[];
    uint32_t* AH = sm + SW_AH;
    uint32_t* AL = sm + SW_AL;
    uint32_t* WH = sm + SW_WH;
    uint32_t* WL = sm + SW_WL;
    float* sb2  = (float*)(sm + SW_SB2);
    float* sbwl = (float*)(sm + SW_SBWL);
    float* scol = (float*)(sm + SW_SCOL);
    float* ssq  = (float*)(sm + SW_SSQ);
    int*   sdeg = (int*)(sm + SW_SDEG);

    const float* hprev = (sel == 0) ? hext : (sel == 1 ? (const float*)g_x : (const float*)g_y);
    float* hout = hext_out ? hext_out : (sel == 0 ? (float*)g_x : (float*)g_y);
    int tid = threadIdx.x;
    int wid = tid >> 5;    // 0..7
    int lid = tid & 31;
    int tq = lid >> 2;
    int tr = lid & 3;
    int row0 = blockIdx.x * 64;
    int m0 = (wid >> 2) * 32;   // 2 m-warps x 4 n-warps, warp tile 32x32
    int n0 = (wid & 3) * 32;

    if (tid < 128) {
        sb2[tid] = g_b2[tid];
        sbwl[tid] = g_bwl[tid];
        scol[tid] = 0.f;
        ssq[tid] = 0.f;
    }
    if (tid < 64) {
        int m = row0 + tid;
        sdeg[tid] = (m < NN) ? (g_rowptr[m + 1] > g_rowptr[m] ? 1 : 0) : 0;
    }

    float c[2][4][4];
#pragma unroll
    for (int i = 0; i < 2; i++)
#pragma unroll
        for (int j = 0; j < 4; j++)
#pragma unroll
            for (int r = 0; r < 4; r++) c[i][j][r] = 0.f;

#pragma unroll
    for (int chunk = 0; chunk < 2; chunk++) {
        const float* Asrc = chunk ? hprev : (const float*)g_agg;
        const uint32_t* Wh = chunk ? (const uint32_t*)g_wrh : (const uint32_t*)g_wlh;
        const uint32_t* Wlo = chunk ? (const uint32_t*)g_wrl : (const uint32_t*)g_wll;
        __syncthreads();   // also covers initial smem setup
        // A fill: split 64 rows (vectorized float4 -> 2 packed words)
        for (int p = tid; p < 2048; p += GT) {
            int r = p >> 5;            // 0..63
            int j2 = (p & 31) * 2;     // 0,2,..,62
            int srow = min(row0 + r, NN - 1);
            float4 v = *(const float4*)(Asrc + (size_t)srow * DD + j2 * 2);
            uint32_t h0, l0, h1, l1;
            split2(v.x, v.y, h0, l0);
            split2(v.z, v.w, h1, l1);
            *(uint2*)&AH[r * AW_STRIDE + j2] = make_uint2(h0, h1);
            *(uint2*)&AL[r * AW_STRIDE + j2] = make_uint2(l0, l1);
        }
        // W fill: pure uint4 copy of pre-split tiles
        for (int p = tid; p < 2048; p += GT) {
            int r = p >> 4;            // 0..127
            int j4 = (p & 15) * 4;     // 0,4,..,60
            *(uint4*)&WH[r * AW_STRIDE + j4] = *(const uint4*)&Wh[r * 64 + j4];
            *(uint4*)&WL[r * AW_STRIDE + j4] = *(const uint4*)&Wlo[r * 64 + j4];
        }
        __syncthreads();
#pragma unroll
        for (int term = 0; term < 3; term++) {
            const uint32_t* Ap = (term == 2) ? AL : AH;
            const uint32_t* Wp = (term == 1) ? WL : WH;
#pragma unroll
            for (int step = 0; step < 8; step++) {
                int kw = step * 8 + tr;
                uint32_t bfr[4][2];
#pragma unroll
                for (int nf = 0; nf < 4; nf++) {
                    const uint32_t* bp = Wp + (n0 + nf * 8 + tq) * AW_STRIDE;
                    bfr[nf][0] = bp[kw];
                    bfr[nf][1] = bp[kw + 4];
                }
#pragma unroll
                for (int mf = 0; mf < 2; mf++) {
                    const uint32_t* ap0 = Ap + (m0 + mf * 16 + tq) * AW_STRIDE;
                    const uint32_t* ap1 = ap0 + 8 * AW_STRIDE;
                    uint32_t a0 = ap0[kw];
                    uint32_t a1 = ap1[kw];
                    uint32_t a2 = ap0[kw + 4];
                    uint32_t a3 = ap1[kw + 4];
#pragma unroll
                    for (int nf = 0; nf < 4; nf++)
                        mma_bf16(c[mf][nf], a0, a1, a2, a3, bfr[nf][0], bfr[nf][1]);
                }
            }
        }
    }

    // ---------- epilogue: folded bias + deg term + ELU + store (+fp16 mirror) + stats ----------
    float cs[4][2], cq[4][2];
#pragma unroll
    for (int nf = 0; nf < 4; nf++) { cs[nf][0] = cs[nf][1] = cq[nf][0] = cq[nf][1] = 0.f; }

#pragma unroll
    for (int mf = 0; mf < 2; mf++) {
        int nl0 = m0 + mf * 16 + tq;
        int m = row0 + nl0;
        int m2 = m + 8;
        int d0 = sdeg[nl0];
        int d1 = sdeg[nl0 + 8];
#pragma unroll
        for (int nf = 0; nf < 4; nf++) {
            int n = n0 + nf * 8 + tr * 2;
            float base0 = sb2[n], base1 = sb2[n + 1];
            float w0 = sbwl[n], w1 = sbwl[n + 1];
            float v0 = c[mf][nf][0] + base0 + (d0 ? w0 : 0.f);
            float v1 = c[mf][nf][1] + base1 + (d0 ? w1 : 0.f);
            float v2 = c[mf][nf][2] + base0 + (d1 ? w0 : 0.f);
            float v3 = c[mf][nf][3] + base1 + (d1 ? w1 : 0.f);
            if (apply_elu) {
                v0 = v0 > 0.f ? v0 : expm1f(v0);
                v1 = v1 > 0.f ? v1 : expm1f(v1);
                v2 = v2 > 0.f ? v2 : expm1f(v2);
                v3 = v3 > 0.f ? v3 : expm1f(v3);
            }
            if (m < NN) {
                *(float2*)(hout + (size_t)m * DD + n) = make_float2(v0, v1);
                if (apply_elu)
                    ((__half2*)(g_h16 + (size_t)m * DD))[n >> 1] = __floats2half2_rn(v0, v1);
                cs[nf][0] += v0; cs[nf][1] += v1;
                cq[nf][0] += v0 * v0; cq[nf][1] += v1 * v1;
            }
            if (m2 < NN) {
                *(float2*)(hout + (size_t)m2 * DD + n) = make_float2(v2, v3);
                if (apply_elu)
                    ((__half2*)(g_h16 + (size_t)m2 * DD))[n >> 1] = __floats2half2_rn(v2, v3);
                cs[nf][0] += v2; cs[nf][1] += v3;
                cq[nf][0] += v2 * v2; cq[nf][1] += v3 * v3;
            }
        }
    }
#pragma unroll
    for (int nf = 0; nf < 4; nf++) {
#pragma unroll
        for (int off = 4; off < 32; off <<= 1) {
            cs[nf][0] += __shfl_xor_sync(0xFFFFFFFF, cs[nf][0], off);
            cs[nf][1] += __shfl_xor_sync(0xFFFFFFFF, cs[nf][1], off);
            cq[nf][0] += __shfl_xor_sync(0xFFFFFFFF, cq[nf][0], off);
            cq[nf][1] += __shfl_xor_sync(0xFFFFFFFF, cq[nf][1], off);
        }
        if (lid < 4) {
            int n = n0 + nf * 8 + tr * 2;
            atomicAdd(&scol[n], cs[nf][0]);
            atomicAdd(&scol[n + 1], cs[nf][1]);
            atomicAdd(&ssq[n], cq[nf][0]);
            atomicAdd(&ssq[n + 1], cq[nf][1]);
        }
    }
    __syncthreads();
    if (tid < 128) {
        atomicAdd(&g_colsum[tid], scol[tid]);
        atomicAdd(&g_colsumsq[tid], ssq[tid]);
    }
}

// ================= BN stats -> scale/shift (final layer only) =================
__global__ void k_stats(const float* __restrict__ gamma, const float* __restrict__ beta) {
    int c = threadIdx.x;
    if (c < DD) {
        float mean = g_colsum[c] / (float)NN;
        float var = g_colsumsq[c] / (float)NN - mean * mean;
        float inv = rsqrtf(var + BN_EPS);
        float gi = gamma[c] * inv;
        g_scale[c] = gi;
        g_shift[c] = beta[c] - gi * mean;
    }
}

// ================= final normalize (in place) =================
__global__ void k_norm(float* __restrict__ buf) {
    int i = blockIdx.x * blockDim.x + threadIdx.x;
    int c4 = i & 31;
    float4 v = ((const float4*)buf)[i];
    float4 sc = ((const float4*)g_scale)[c4];
    float4 sh = ((const float4*)g_shift)[c4];
    v.x = v.x * sc.x + sh.x;
    v.y = v.y * sc.y + sh.y;
    v.z = v.z * sc.z + sh.z;
    v.w = v.w * sc.w + sh.w;
    ((float4*)buf)[i] = v;
}

// ================= eager module load =================
namespace {
void* g_deg_ptr = nullptr;
struct HXEagerLoad {
    HXEagerLoad() {
        void* p = nullptr;
        cudaGetSymbolAddress(&p, g_agg);
        cudaGetSymbolAddress(&p, g_x);
        cudaGetSymbolAddress(&p, g_y);
        cudaGetSymbolAddress(&p, g_h16);
        cudaGetSymbolAddress(&p, g_csr);
        cudaGetSymbolAddress(&p, g_wlh);
        cudaGetSymbolAddress(&g_deg_ptr, g_deg);
        cudaFuncAttributes a;
        cudaFuncGetAttributes(&a, k_count_cvt);
        cudaFuncGetAttributes(&a, k_scan);
        cudaFuncGetAttributes(&a, k_fill);
        cudaFuncGetAttributes(&a, k_stats);
        cudaFuncGetAttributes(&a, k_fold);
        cudaFuncGetAttributes(&a, k_agg);
        cudaFuncGetAttributes(&a, k_gemm);
        cudaFuncGetAttributes(&a, k_norm);
        cudaFuncSetAttribute(k_gemm, cudaFuncAttributeMaxDynamicSharedMemorySize, GEMM_SMEM);
        cudaDeviceSynchronize();
    }
};
HXEagerLoad hx_eager_load_;
}  // namespace

// ================= launch =================
extern "C" void kernel_launch(void* const* d_in, const int* in_sizes, int n_in,
                              void* d_out, int out_size) {
    (void)in_sizes; (void)n_in; (void)out_size;
    const float* x  = (const float*)d_in[0];
    const int*   ei = (const int*)d_in[1];
    const float* Wl = (const float*)d_in[2];
    const float* Wr = (const float*)d_in[3];
    const float* b  = (const float*)d_in[4];
    const float* gm = (const float*)d_in[5];
    const float* bt = (const float*)d_in[6];
    float* out = (float*)d_out;
    const int* src = ei;
    const int* dst = ei + EE;

    cudaMemsetAsync(g_deg_ptr, 0, NN * sizeof(int));
    k_count_cvt<<<12500, 256>>>(dst, x);       // count + x->fp16 mirror
    k_scan<<<1, 1024>>>();
    k_fill<<<(EE + 255) / 256, 256>>>(src, dst);

    const int GEMM_GRID = (NN + 63) / 64;  // 1563
    const int AGG_GRID = (NN / 2 + 7) / 8; // 2 nodes/warp, 8 warps/block
    for (int l = 0; l < LL; l++) {
        int sel = (l == 0) ? 0 : (l == 1 ? 1 : 2);
        k_agg<<<AGG_GRID, 256>>>();            // gathers g_h16 (4th kernel launch at l=0)
        k_fold<<<128, 128>>>(Wl + l * DD * DD, Wr + l * DD * DD, b + l * DD,
                             gm + (l - 1) * DD, bt + (l - 1) * DD, l == 0 ? 1 : 0);
        if (l < LL - 1)
            k_gemm<<<GEMM_GRID, GT, GEMM_SMEM>>>(x, sel, 1, nullptr);   // -> g_x / g_y (+h16)
        else
            k_gemm<<<GEMM_GRID, GT, GEMM_SMEM>>>(x, sel, 0, out);       // -> out
    }
    k_stats<<<1, 128>>>(gm + (LL - 1) * DD, bt + (LL - 1) * DD);
    k_norm<<<NN * 32 / 256, 256>>>(out);
}

// round 17
// speedup vs baseline: 1.3955x; 1.2968x over previous
#include <cuda_runtime.h>
#include <cuda_fp16.h>
#include <math.h>
#include <stdint.h>

#define NN 100000
#define EE 800000
#define DD 128
#define LL 3
#define BN_EPS 1e-5f

// ================= scratch =================
// fp16 rows: 128 halfs = 64 uint32 words per row
__device__ __align__(16) uint32_t g_agg16[(size_t)NN * 64];  // fp16 mean-aggregate
__device__ __align__(16) uint32_t g_h16[(size_t)NN * 64];    // fp16 activation mirror
__device__ int g_deg[NN];
__device__ int g_rowptr[NN + 1];
__device__ int g_cursor[NN];
__device__ int g_csr[EE];
__device__ __align__(16) float g_colsum[DD];
__device__ __align__(16) float g_colsumsq[DD];
__device__ __align__(16) float g_scale[DD];
__device__ __align__(16) float g_shift[DD];
// folded W, pre-split into packed fp16 hi/lo pairs, compact stride-64 tile layout
__device__ __align__(16) uint32_t g_wlh[DD * 64];
__device__ __align__(16) uint32_t g_wll[DD * 64];
__device__ __align__(16) uint32_t g_wrh[DD * 64];
__device__ __align__(16) uint32_t g_wrl[DD * 64];
__device__ __align__(16) float g_b2[DD];    // b + sh@Wr^T
__device__ __align__(16) float g_bwl[DD];   // sh@Wl^T (added only when deg>0)

// ================= CSR build (+ x -> fp16 mirror) =================
__global__ void k_count_cvt(const int* __restrict__ dst, const float* __restrict__ x) {
    int t = blockIdx.x * blockDim.x + threadIdx.x;
    if (t < EE) atomicAdd(&g_deg[dst[t]], 1);
    for (int i = t; i < NN * DD / 4; i += gridDim.x * blockDim.x) {
        float4 v = ((const float4*)x)[i];
        __half2* o = (__half2*)g_h16;          // NN*DD/2 half2 = NN*64 words total
        o[i * 2] = __floats2half2_rn(v.x, v.y);
        o[i * 2 + 1] = __floats2half2_rn(v.z, v.w);
    }
}
__global__ void k_scan() {
    __shared__ int sh[1024];
    int t = threadIdx.x;
    const int CH = (NN + 1023) / 1024;
    int beg = t * CH;
    int end = min(beg + CH, NN);
    int s = 0;
    for (int i = beg; i < end; i++) s += g_deg[i];
    sh[t] = s;
    __syncthreads();
    for (int off = 1; off < 1024; off <<= 1) {
        int v = (t >= off) ? sh[t - off] : 0;
        __syncthreads();
        sh[t] += v;
        __syncthreads();
    }
    int run = sh[t] - s;
    for (int i = beg; i < end; i++) {
        g_rowptr[i] = run;
        g_cursor[i] = run;
        run += g_deg[i];
    }
    if (t == 1023) g_rowptr[NN] = sh[1023];
}
__global__ void k_fill(const int* __restrict__ src, const int* __restrict__ dst) {
    int e = blockIdx.x * blockDim.x + threadIdx.x;
    if (e < EE) {
        int d = dst[e];
        int p = atomicAdd(&g_cursor[d], 1);
        g_csr[p] = src[e];
    }
}

// ================= fp16 split helper =================
__device__ __forceinline__ void split1h(float x, uint32_t& hi, uint32_t& lo) {
    __half h = __float2half_rn(x);
    __half l = __float2half_rn(x - __half2float(h));
    hi = (uint32_t)__half_as_ushort(h);
    lo = (uint32_t)__half_as_ushort(l);
}

// ================= fold: BN(prev stats) into W; emit packed fp16 split tiles + bias ========
__global__ void k_fold(const float* __restrict__ Wl, const float* __restrict__ Wr,
                       const float* __restrict__ b,
                       const float* __restrict__ gamma, const float* __restrict__ beta,
                       int ident) {
    __shared__ float red[8];
    int o = blockIdx.x;       // 0..127 output row
    int i = threadIdx.x;      // 0..127 input col
    float sc = 1.f, sh = 0.f;
    if (!ident) {
        float mean = g_colsum[i] / (float)NN;
        float var = g_colsumsq[i] / (float)NN - mean * mean;
        float inv = rsqrtf(var + BN_EPS);
        sc = gamma[i] * inv;
        sh = beta[i] - sc * mean;
    }
    float wl = Wl[o * DD + i];
    float wr = Wr[o * DD + i];
    float wls = wl * sc;
    float wrs = wr * sc;
    if (o == 0) { g_colsum[i] = 0.f; g_colsumsq[i] = 0.f; }

    uint32_t lh, ll, rh, rl;
    split1h(wls, lh, ll);
    split1h(wrs, rh, rl);
    uint32_t lh1 = __shfl_down_sync(0xFFFFFFFF, lh, 1);
    uint32_t ll1 = __shfl_down_sync(0xFFFFFFFF, ll, 1);
    uint32_t rh1 = __shfl_down_sync(0xFFFFFFFF, rh, 1);
    uint32_t rl1 = __shfl_down_sync(0xFFFFFFFF, rl, 1);
    if ((i & 1) == 0) {
        int w = o * 64 + (i >> 1);
        g_wlh[w] = lh | (lh1 << 16);
        g_wll[w] = ll | (ll1 << 16);
        g_wrh[w] = rh | (rh1 << 16);
        g_wrl[w] = rl | (rl1 << 16);
    }
    float a = sh * wl, c2 = sh * wr;
#pragma unroll
    for (int off = 16; off > 0; off >>= 1) {
        a += __shfl_down_sync(0xFFFFFFFF, a, off);
        c2 += __shfl_down_sync(0xFFFFFFFF, c2, off);
    }
    int wid = i >> 5, lid = i & 31;
    if (lid == 0) { red[wid] = a; red[4 + wid] = c2; }
    __syncthreads();
    if (i == 0) {
        g_b2[o] = b[o] + red[4] + red[5] + red[6] + red[7];
        g_bwl[o] = red[0] + red[1] + red[2] + red[3];
    }
}

// ================= aggregation: fp16 gather, 2 nodes/warp interleaved (MLP=8) =============
// lane owns 4 features = 2 words = 1 uint2; row stride = 64 words
__device__ __forceinline__ void acc_h4(float4& a, uint2 u) {
    float2 f0 = __half22float2(*(__half2*)&u.x);
    float2 f1 = __half22float2(*(__half2*)&u.y);
    a.x += f0.x; a.y += f0.y; a.z += f1.x; a.w += f1.y;
}

__global__ void k_agg() {
    int warp = (blockIdx.x * blockDim.x + threadIdx.x) >> 5;
    int lane = threadIdx.x & 31;
    int nA = warp * 2;
    int nB = nA + 1;
    if (nA >= NN) return;
    int ea = g_rowptr[nA];
    int s1a = g_rowptr[nA + 1];
    int eb = 0, s1b = 0;
    if (nB < NN) { eb = g_rowptr[nB]; s1b = g_rowptr[nB + 1]; }
    int degA = s1a - ea;
    int degB = s1b - eb;

    float4 aA0 = make_float4(0.f, 0.f, 0.f, 0.f), aA1 = aA0;
    float4 aB0 = aA0, aB1 = aA0;

    while (ea + 4 <= s1a && eb + 4 <= s1b) {
        int i0 = g_csr[ea], i1 = g_csr[ea + 1], i2 = g_csr[ea + 2], i3 = g_csr[ea + 3];
        int j0 = g_csr[eb], j1 = g_csr[eb + 1], j2 = g_csr[eb + 2], j3 = g_csr[eb + 3];
        uint2 u0 = *(const uint2*)(g_h16 + (size_t)i0 * 64 + lane * 2);
        uint2 u1 = *(const uint2*)(g_h16 + (size_t)i1 * 64 + lane * 2);
        uint2 u2 = *(const uint2*)(g_h16 + (size_t)i2 * 64 + lane * 2);
        uint2 u3 = *(const uint2*)(g_h16 + (size_t)i3 * 64 + lane * 2);
        uint2 w0 = *(const uint2*)(g_h16 + (size_t)j0 * 64 + lane * 2);
        uint2 w1 = *(const uint2*)(g_h16 + (size_t)j1 * 64 + lane * 2);
        uint2 w2 = *(const uint2*)(g_h16 + (size_t)j2 * 64 + lane * 2);
        uint2 w3 = *(const uint2*)(g_h16 + (size_t)j3 * 64 + lane * 2);
        acc_h4(aA0, u0); acc_h4(aA1, u1); acc_h4(aA0, u2); acc_h4(aA1, u3);
        acc_h4(aB0, w0); acc_h4(aB1, w1); acc_h4(aB0, w2); acc_h4(aB1, w3);
        ea += 4;
        eb += 4;
    }
    for (; ea + 4 <= s1a; ea += 4) {
        int i0 = g_csr[ea], i1 = g_csr[ea + 1], i2 = g_csr[ea + 2], i3 = g_csr[ea + 3];
        uint2 u0 = *(const uint2*)(g_h16 + (size_t)i0 * 64 + lane * 2);
        uint2 u1 = *(const uint2*)(g_h16 + (size_t)i1 * 64 + lane * 2);
        uint2 u2 = *(const uint2*)(g_h16 + (size_t)i2 * 64 + lane * 2);
        uint2 u3 = *(const uint2*)(g_h16 + (size_t)i3 * 64 + lane * 2);
        acc_h4(aA0, u0); acc_h4(aA1, u1); acc_h4(aA0, u2); acc_h4(aA1, u3);
    }
    for (; ea < s1a; ea++) {
        uint2 u0 = *(const uint2*)(g_h16 + (size_t)g_csr[ea] * 64 + lane * 2);
        acc_h4(aA0, u0);
    }
    for (; eb + 4 <= s1b; eb += 4) {
        int j0 = g_csr[eb], j1 = g_csr[eb + 1], j2 = g_csr[eb + 2], j3 = g_csr[eb + 3];
        uint2 w0 = *(const uint2*)(g_h16 + (size_t)j0 * 64 + lane * 2);
        uint2 w1 = *(const uint2*)(g_h16 + (size_t)j1 * 64 + lane * 2);
        uint2 w2 = *(const uint2*)(g_h16 + (size_t)j2 * 64 + lane * 2);
        uint2 w3 = *(const uint2*)(g_h16 + (size_t)j3 * 64 + lane * 2);
        acc_h4(aB0, w0); acc_h4(aB1, w1); acc_h4(aB0, w2); acc_h4(aB1, w3);
    }
    for (; eb < s1b; eb++) {
        uint2 w0 = *(const uint2*)(g_h16 + (size_t)g_csr[eb] * 64 + lane * 2);
        acc_h4(aB0, w0);
    }

    float invA = 1.0f / (float)max(degA, 1);
    uint2 oA;
    *(__half2*)&oA.x = __floats2half2_rn((aA0.x + aA1.x) * invA, (aA0.y + aA1.y) * invA);
    *(__half2*)&oA.y = __floats2half2_rn((aA0.z + aA1.z) * invA, (aA0.w + aA1.w) * invA);
    *(uint2*)(g_agg16 + (size_t)nA * 64 + lane * 2) = oA;
    if (nB < NN) {
        float invB = 1.0f / (float)max(degB, 1);
        uint2 oB;
        *(__half2*)&oB.x = __floats2half2_rn((aB0.x + aB1.x) * invB, (aB0.y + aB1.y) * invB);
        *(__half2*)&oB.y = __floats2half2_rn((aB0.z + aB1.z) * invB, (aB0.w + aB1.w) * invB);
        *(uint2*)(g_agg16 + (size_t)nB * 64 + lane * 2) = oB;
    }
}

// ================= fp16 HMMA GEMM: A single fp16, W split fp16, 2 terms =================
#define AW_STRIDE 68
#define A_WORDS (64 * AW_STRIDE)      // A tile: 64 rows x 64 words (stride 68)
#define W_WORDS (128 * AW_STRIDE)     // W tile: 128 rows x 64 words
#define SW_AH 0
#define SW_WH (SW_AH + A_WORDS)
#define SW_WL (SW_WH + W_WORDS)
#define SW_SB2  (SW_WL + W_WORDS)
#define SW_SBWL (SW_SB2 + 128)
#define SW_SCOL (SW_SBWL + 128)
#define SW_SSQ  (SW_SCOL + 128)
#define SW_SDEG (SW_SSQ + 128)
#define GEMM_SMEM ((SW_SDEG + 64) * 4)   // 89,344 bytes
#define GT 256

__device__ __forceinline__ void mma_f16(float* c, uint32_t a0, uint32_t a1, uint32_t a2,
                                        uint32_t a3, uint32_t b0, uint32_t b1) {
    asm volatile(
        "mma.sync.aligned.m16n8k16.row.col.f32.f16.f16.f32 "
        "{%0,%1,%2,%3}, {%4,%5,%6,%7}, {%8,%9}, {%0,%1,%2,%3};"
        : "+f"(c[0]), "+f"(c[1]), "+f"(c[2]), "+f"(c[3])
        : "r"(a0), "r"(a1), "r"(a2), "r"(a3), "r"(b0), "r"(b1));
}

__global__ void __launch_bounds__(GT, 2) k_gemm(int apply_elu, float* __restrict__ outp) {
    extern __shared__ __align__(16) uint32_t sm[];
    uint32_t* AH = sm + SW_AH;
    uint32_t* WH = sm + SW_WH;
    uint32_t* WL = sm + SW_WL;
    float* sb2  = (float*)(sm + SW_SB2);
    float* sbwl = (float*)(sm + SW_SBWL);
    float* scol = (float*)(sm + SW_SCOL);
    float* ssq  = (float*)(sm + SW_SSQ);
    int*   sdeg = (int*)(sm + SW_SDEG);

    int tid = threadIdx.x;
    int wid = tid >> 5;    // 0..7
    int lid = tid & 31;
    int tq = lid >> 2;
    int tr = lid & 3;
    int row0 = blockIdx.x * 64;
    int m0 = (wid >> 2) * 32;   // 2 m-warps x 4 n-warps, warp tile 32x32
    int n0 = (wid & 3) * 32;

    if (tid < 128) {
        sb2[tid] = g_b2[tid];
        sbwl[tid] = g_bwl[tid];
        scol[tid] = 0.f;
        ssq[tid] = 0.f;
    }
    if (tid < 64) {
        int m = row0 + tid;
        sdeg[tid] = (m < NN) ? (g_rowptr[m + 1] > g_rowptr[m] ? 1 : 0) : 0;
    }

    float c[2][4][4];
#pragma unroll
    for (int i = 0; i < 2; i++)
#pragma unroll
        for (int j = 0; j < 4; j++)
#pragma unroll
            for (int r = 0; r < 4; r++) c[i][j][r] = 0.f;

#pragma unroll
    for (int chunk = 0; chunk < 2; chunk++) {
        const uint32_t* Asrc = chunk ? (const uint32_t*)g_h16 : (const uint32_t*)g_agg16;
        const uint32_t* Wh = chunk ? (const uint32_t*)g_wrh : (const uint32_t*)g_wlh;
        const uint32_t* Wlo = chunk ? (const uint32_t*)g_wrl : (const uint32_t*)g_wll;
        __syncthreads();   // also covers initial smem setup
        // A fill: pure uint4 copy, 64 rows x 64 words (16 uint4 per row)
        for (int p = tid; p < 1024; p += GT) {
            int r = p >> 4;            // 0..63
            int j4 = (p & 15) * 4;     // 0,4,..,60
            int srow = min(row0 + r, NN - 1);
            *(uint4*)&AH[r * AW_STRIDE + j4] = *(const uint4*)&Asrc[(size_t)srow * 64 + j4];
        }
        // W fill: pure uint4 copy of pre-split fp16 tiles (128 rows x 64 words)
        for (int p = tid; p < 2048; p += GT) {
            int r = p >> 4;            // 0..127
            int j4 = (p & 15) * 4;     // 0,4,..,60
            *(uint4*)&WH[r * AW_STRIDE + j4] = *(const uint4*)&Wh[r * 64 + j4];
            *(uint4*)&WL[r * AW_STRIDE + j4] = *(const uint4*)&Wlo[r * 64 + j4];
        }
        __syncthreads();
#pragma unroll
        for (int term = 0; term < 2; term++) {
            const uint32_t* Wp = term ? WL : WH;
#pragma unroll
            for (int step = 0; step < 8; step++) {
                int kw = step * 8 + tr;
                uint32_t bfr[4][2];
#pragma unroll
                for (int nf = 0; nf < 4; nf++) {
                    const uint32_t* bp = Wp + (n0 + nf * 8 + tq) * AW_STRIDE;
                    bfr[nf][0] = bp[kw];
                    bfr[nf][1] = bp[kw + 4];
                }
#pragma unroll
                for (int mf = 0; mf < 2; mf++) {
                    const uint32_t* ap0 = AH + (m0 + mf * 16 + tq) * AW_STRIDE;
                    const uint32_t* ap1 = ap0 + 8 * AW_STRIDE;
                    uint32_t a0 = ap0[kw];
                    uint32_t a1 = ap1[kw];
                    uint32_t a2 = ap0[kw + 4];
                    uint32_t a3 = ap1[kw + 4];
#pragma unroll
                    for (int nf = 0; nf < 4; nf++)
                        mma_f16(c[mf][nf], a0, a1, a2, a3, bfr[nf][0], bfr[nf][1]);
                }
            }
        }
    }

    // ---------- epilogue: folded bias + deg term + ELU + store + fused stats ----------
    float cs[4][2], cq[4][2];
#pragma unroll
    for (int nf = 0; nf < 4; nf++) { cs[nf][0] = cs[nf][1] = cq[nf][0] = cq[nf][1] = 0.f; }

#pragma unroll
    for (int mf = 0; mf < 2; mf++) {
        int nl0 = m0 + mf * 16 + tq;
        int m = row0 + nl0;
        int m2 = m + 8;
        int d0 = sdeg[nl0];
        int d1 = sdeg[nl0 + 8];
#pragma unroll
        for (int nf = 0; nf < 4; nf++) {
            int n = n0 + nf * 8 + tr * 2;
            float base0 = sb2[n], base1 = sb2[n + 1];
            float w0 = sbwl[n], w1 = sbwl[n + 1];
            float v0 = c[mf][nf][0] + base0 + (d0 ? w0 : 0.f);
            float v1 = c[mf][nf][1] + base1 + (d0 ? w1 : 0.f);
            float v2 = c[mf][nf][2] + base0 + (d1 ? w0 : 0.f);
            float v3 = c[mf][nf][3] + base1 + (d1 ? w1 : 0.f);
            if (apply_elu) {
                v0 = v0 > 0.f ? v0 : expm1f(v0);
                v1 = v1 > 0.f ? v1 : expm1f(v1);
                v2 = v2 > 0.f ? v2 : expm1f(v2);
                v3 = v3 > 0.f ? v3 : expm1f(v3);
            }
            if (m < NN) {
                if (outp)
                    *(float2*)(outp + (size_t)m * DD + n) = make_float2(v0, v1);
                else
                    ((__half2*)(g_h16 + (size_t)m * 64))[n >> 1] = __floats2half2_rn(v0, v1);
                cs[nf][0] += v0; cs[nf][1] += v1;
                cq[nf][0] += v0 * v0; cq[nf][1] += v1 * v1;
            }
            if (m2 < NN) {
                if (outp)
                    *(float2*)(outp + (size_t)m2 * DD + n) = make_float2(v2, v3);
                else
                    ((__half2*)(g_h16 + (size_t)m2 * 64))[n >> 1] = __floats2half2_rn(v2, v3);
                cs[nf][0] += v2; cs[nf][1] += v3;
                cq[nf][0] += v2 * v2; cq[nf][1] += v3 * v3;
            }
        }
    }
#pragma unroll
    for (int nf = 0; nf < 4; nf++) {
#pragma unroll
        for (int off = 4; off < 32; off <<= 1) {
            cs[nf][0] += __shfl_xor_sync(0xFFFFFFFF, cs[nf][0], off);
            cs[nf][1] += __shfl_xor_sync(0xFFFFFFFF, cs[nf][1], off);
            cq[nf][0] += __shfl_xor_sync(0xFFFFFFFF, cq[nf][0], off);
            cq[nf][1] += __shfl_xor_sync(0xFFFFFFFF, cq[nf][1], off);
        }
        if (lid < 4) {
            int n = n0 + nf * 8 + tr * 2;
            atomicAdd(&scol[n], cs[nf][0]);
            atomicAdd(&scol[n + 1], cs[nf][1]);
            atomicAdd(&ssq[n], cq[nf][0]);
            atomicAdd(&ssq[n + 1], cq[nf][1]);
        }
    }
    __syncthreads();
    if (tid < 128) {
        atomicAdd(&g_colsum[tid], scol[tid]);
        atomicAdd(&g_colsumsq[tid], ssq[tid]);
    }
}

// ================= BN stats -> scale/shift (final layer only) =================
__global__ void k_stats(const float* __restrict__ gamma, const float* __restrict__ beta) {
    int c = threadIdx.x;
    if (c < DD) {
        float mean = g_colsum[c] / (float)NN;
        float var = g_colsumsq[c] / (float)NN - mean * mean;
        float inv = rsqrtf(var + BN_EPS);
        float gi = gamma[c] * inv;
        g_scale[c] = gi;
        g_shift[c] = beta[c] - gi * mean;
    }
}

// ================= final normalize (in place) =================
__global__ void k_norm(float* __restrict__ buf) {
    int i = blockIdx.x * blockDim.x + threadIdx.x;
    int c4 = i & 31;
    float4 v = ((const float4*)buf)[i];
    float4 sc = ((const float4*)g_scale)[c4];
    float4 sh = ((const float4*)g_shift)[c4];
    v.x = v.x * sc.x + sh.x;
    v.y = v.y * sc.y + sh.y;
    v.z = v.z * sc.z + sh.z;
    v.w = v.w * sc.w + sh.w;
    ((float4*)buf)[i] = v;
}

// ================= eager module load =================
namespace {
void* g_deg_ptr = nullptr;
struct HXEagerLoad {
    HXEagerLoad() {
        void* p = nullptr;
        cudaGetSymbolAddress(&p, g_agg16);
        cudaGetSymbolAddress(&p, g_h16);
        cudaGetSymbolAddress(&p, g_csr);
        cudaGetSymbolAddress(&p, g_wlh);
        cudaGetSymbolAddress(&g_deg_ptr, g_deg);
        cudaFuncAttributes a;
        cudaFuncGetAttributes(&a, k_count_cvt);
        cudaFuncGetAttributes(&a, k_scan);
        cudaFuncGetAttributes(&a, k_fill);
        cudaFuncGetAttributes(&a, k_stats);
        cudaFuncGetAttributes(&a, k_fold);
        cudaFuncGetAttributes(&a, k_agg);
        cudaFuncGetAttributes(&a, k_gemm);
        cudaFuncGetAttributes(&a, k_norm);
        cudaFuncSetAttribute(k_gemm, cudaFuncAttributeMaxDynamicSharedMemorySize, GEMM_SMEM);
        cudaDeviceSynchronize();
    }
};
HXEagerLoad hx_eager_load_;
}  // namespace

// ================= launch =================
extern "C" void kernel_launch(void* const* d_in, const int* in_sizes, int n_in,
                              void* d_out, int out_size) {
    (void)in_sizes; (void)n_in; (void)out_size;
    const float* x  = (const float*)d_in[0];
    const int*   ei = (const int*)d_in[1];
    const float* Wl = (const float*)d_in[2];
    const float* Wr = (const float*)d_in[3];
    const float* b  = (const float*)d_in[4];
    const float* gm = (const float*)d_in[5];
    const float* bt = (const float*)d_in[6];
    float* out = (float*)d_out;
    const int* src = ei;
    const int* dst = ei + EE;

    cudaMemsetAsync(g_deg_ptr, 0, NN * sizeof(int));
    k_count_cvt<<<12500, 256>>>(dst, x);       // count + x->fp16 mirror
    k_scan<<<1, 1024>>>();
    k_fill<<<(EE + 255) / 256, 256>>>(src, dst);

    const int GEMM_GRID = (NN + 63) / 64;  // 1563
    const int AGG_GRID = (NN / 2 + 7) / 8; // 2 nodes/warp, 8 warps/block
    for (int l = 0; l < LL; l++) {
        k_agg<<<AGG_GRID, 256>>>();            // g_h16 -> g_agg16
        k_fold<<<128, 128>>>(Wl + l * DD * DD, Wr + l * DD * DD, b + l * DD,
                             gm + (l - 1) * DD, bt + (l - 1) * DD, l == 0 ? 1 : 0);
        if (l < LL - 1)
            k_gemm<<<GEMM_GRID, GT, GEMM_SMEM>>>(1, nullptr);   // -> g_h16 (fp16 mirror)
        else
            k_gemm<<<GEMM_GRID, GT, GEMM_SMEM>>>(0, out);       // -> fp32 out
    }
    k_stats<<<1, 128>>>(gm + (LL - 1) * DD, bt + (LL - 1) * DD);
    k_norm<<<NN * 32 / 256, 256>>>(out);
}